// round 12
// baseline (speedup 1.0000x reference)
#include <cuda_runtime.h>
#include <cuda_bf16.h>
#include <cuda_fp16.h>
#include <math_constants.h>
#include <cstdint>

// ---------------------------------------------------------------------------
// MHA Round 12: attention warps widened to M=32 rows (4 warps / 128-thread
// CTA) so K/V fragments are shared across two m-frags -> smem read traffic
// halves. Packed f16x2 converts. GEMMs unchanged from R11.
// ---------------------------------------------------------------------------

#define BATCH 4
#define SEQ   2048
#define DM    1024
#define NH    16
#define HD    64
#define MROWS (BATCH * SEQ)
#define ATT_SCALE 0.125f
#define LOG2E 1.44269504088896340736f

#define BM 128
#define BN 128
#define BK 32
#define NCH (DM / BK)
#define GSTAGES 4
#define PITCH 40
#define TILE_B (128 * PITCH * 2)            // 10240
#define GEMM_SMEM (GSTAGES * 2 * TILE_B)    // 81920

// attention smem
#define APITCH 72
#define AQ_B   (128 * APITCH * 2)           // 18432 (single Q)
#define AK_B   (64 * APITCH * 2)            // 9216 per K/V tile
#define ASTG_B (2 * AK_B)                   // 18432 per stage (K, V)
#define ASTAGES 3
#define AOFF_Q  0
#define AOFF_ST AQ_B                          // 18432
#define AOFF_PM (AOFF_ST + ASTAGES * ASTG_B)  // 73728
#define ATTN_SMEM (AOFF_PM + 768)             // 74496
#define ATHREADS 128

// ---- scratch ----------------------------------------------------------------
__device__ __align__(256) __half g_x [MROWS * DM];
__device__ __align__(256) __half g_q [MROWS * DM];
__device__ __align__(256) __half g_k [MROWS * DM];
__device__ __align__(256) __half g_v [MROWS * DM];
__device__ __align__(256) __half g_a [MROWS * DM];
__device__ __align__(256) __half g_wf[4][DM * DM];        // W^T fp16: q,k,v,o

// ---- helpers ------------------------------------------------------------------
__device__ __forceinline__ uint32_t smem_to_u32(const void* p) {
    uint32_t a;
    asm("{ .reg .u64 t; cvta.to.shared.u64 t, %1; cvt.u32.u64 %0, t; }"
        : "=r"(a) : "l"(p));
    return a;
}
__device__ __forceinline__ void mma_f16(float* d, const uint32_t* a, const uint32_t* b) {
    asm volatile(
        "mma.sync.aligned.m16n8k16.row.col.f32.f16.f16.f32 "
        "{%0,%1,%2,%3}, {%4,%5,%6,%7}, {%8,%9}, {%0,%1,%2,%3};\n"
        : "+f"(d[0]), "+f"(d[1]), "+f"(d[2]), "+f"(d[3])
        : "r"(a[0]), "r"(a[1]), "r"(a[2]), "r"(a[3]), "r"(b[0]), "r"(b[1]));
}
__device__ __forceinline__ void ldsm_x4(uint32_t* r, uint32_t addr) {
    asm volatile("ldmatrix.sync.aligned.m8n8.x4.shared.b16 {%0,%1,%2,%3}, [%4];"
        : "=r"(r[0]), "=r"(r[1]), "=r"(r[2]), "=r"(r[3]) : "r"(addr));
}
__device__ __forceinline__ void ldsm_x4_t(uint32_t* r, uint32_t addr) {
    asm volatile("ldmatrix.sync.aligned.m8n8.x4.trans.shared.b16 {%0,%1,%2,%3}, [%4];"
        : "=r"(r[0]), "=r"(r[1]), "=r"(r[2]), "=r"(r[3]) : "r"(addr));
}
__device__ __forceinline__ void cpasync16(uint32_t dst, const void* src) {
    asm volatile("cp.async.cg.shared.global [%0], [%1], 16;" :: "r"(dst), "l"(src));
}
__device__ __forceinline__ uint32_t pack_h2(__half a, __half b) {
    __half2 t = __halves2half2(a, b);
    return *(uint32_t*)&t;
}
// packed convert: d = {lo=f_lo, hi=f_hi} in one cvt
__device__ __forceinline__ uint32_t cvt_f16x2(float f_lo, float f_hi) {
    uint32_t r;
    asm("cvt.rn.f16x2.f32 %0, %1, %2;" : "=r"(r) : "f"(f_hi), "f"(f_lo));
    return r;
}

// ---- GEMM body (unchanged from R11): single-pass fp16, 4-stage pipeline ---------
template<int OMODE>
__device__ __forceinline__ void gemm_body(
    const __half* A_, const __half* B_,
    float* __restrict__ C, __half* __restrict__ Ch, float scale)
{
    constexpr int STAGE_B = 2 * TILE_B;
    extern __shared__ char smem[];
    const uint32_t sb = smem_to_u32(smem);
    const int tid  = threadIdx.x;
    const int lane = tid & 31;
    const int wid  = tid >> 5;
    const int wm   = wid >> 2;
    const int wn   = wid & 3;
    const int bm = blockIdx.y, bn = blockIdx.x;

    const __half* gsrc[2] = {
        A_ + (size_t)bm * BM * DM,
        B_ + (size_t)bn * BN * DM
    };

    float acc[4][4][4];
#pragma unroll
    for (int i = 0; i < 4; i++)
#pragma unroll
        for (int j = 0; j < 4; j++)
#pragma unroll
            for (int r = 0; r < 4; r++) acc[i][j][r] = 0.f;

    auto issue = [&](int c) {
        if (c < NCH) {
            const uint32_t sbase = sb + (c % GSTAGES) * STAGE_B;
            const size_t koff = (size_t)c * BK;
#pragma unroll
            for (int i = 0; i < 4; i++) {
                int q = tid + i * 256;
                int t = q >> 9, r = (q >> 2) & 127, c16 = q & 3;
                cpasync16(sbase + t * TILE_B + (r * PITCH + c16 * 8) * 2,
                          gsrc[t] + (size_t)r * DM + koff + c16 * 8);
            }
        }
        asm volatile("cp.async.commit_group;");
    };

    issue(0); issue(1); issue(2);

    const int a_r = (lane & 7) + ((lane >> 3) & 1) * 8;
    const int a_c = (lane >> 4) * 8;
    const int b_r = (lane & 7) + ((lane >> 4) & 1) * 8;
    const int b_c = ((lane >> 3) & 1) * 8;

    for (int c = 0; c < NCH; c++) {
        asm volatile("cp.async.wait_group %0;" :: "n"(GSTAGES - 2));
        __syncthreads();
        issue(c + GSTAGES - 1);

        const uint32_t st = sb + (c % GSTAGES) * STAGE_B;
        const uint32_t sA = st, sB = st + TILE_B;

#pragma unroll
        for (int k16 = 0; k16 < 2; k16++) {
            const int kc = k16 * 16;
            uint32_t ah[4][4], bh[2][4];
#pragma unroll
            for (int mfi = 0; mfi < 4; mfi++)
                ldsm_x4(ah[mfi], sA + ((wm * 64 + mfi * 16 + a_r) * PITCH + kc + a_c) * 2);
#pragma unroll
            for (int nfp = 0; nfp < 2; nfp++)
                ldsm_x4(bh[nfp], sB + ((wn * 32 + nfp * 16 + b_r) * PITCH + kc + b_c) * 2);
#pragma unroll
            for (int mfi = 0; mfi < 4; mfi++)
#pragma unroll
                for (int nf = 0; nf < 4; nf++)
                    mma_f16(acc[mfi][nf], ah[mfi], &bh[nf >> 1][(nf & 1) * 2]);
        }
    }

#pragma unroll
    for (int mfi = 0; mfi < 4; mfi++)
#pragma unroll
        for (int nf = 0; nf < 4; nf++) {
            int row = bm * BM + wm * 64 + mfi * 16 + (lane >> 2);
            int col = bn * BN + wn * 32 + nf * 8 + (lane & 3) * 2;
            float v0 = acc[mfi][nf][0] * scale, v1 = acc[mfi][nf][1] * scale;
            float v2 = acc[mfi][nf][2] * scale, v3 = acc[mfi][nf][3] * scale;
            if (OMODE == 0) {
                *(float2*)&C[(size_t)row * DM + col]       = make_float2(v0, v1);
                *(float2*)&C[(size_t)(row + 8) * DM + col] = make_float2(v2, v3);
            } else {
                *(uint32_t*)&Ch[(size_t)row * DM + col]       = cvt_f16x2(v0, v1);
                *(uint32_t*)&Ch[(size_t)(row + 8) * DM + col] = cvt_f16x2(v2, v3);
            }
        }
}

__global__ __launch_bounds__(256, 2)
void qkv_mma_kernel()
{
    const int z = blockIdx.z;
    if (z == 0)
        gemm_body<2>(g_x, g_wf[0], nullptr, g_q, ATT_SCALE * LOG2E);
    else if (z == 1)
        gemm_body<2>(g_x, g_wf[1], nullptr, g_k, 1.f);
    else
        gemm_body<2>(g_x, g_wf[2], nullptr, g_v, 1.f);
}
__global__ __launch_bounds__(256, 2)
void out_mma_kernel(float* __restrict__ out)
{
    gemm_body<0>(g_a, g_wf[3], out, nullptr, 1.f);
}

// ---- conversions --------------------------------------------------------------
__global__ __launch_bounds__(256) void conv_x_kernel(const float* __restrict__ s) {
    int i = blockIdx.x * 256 + threadIdx.x;
    float4 v = ((const float4*)s)[i];
    ((uint32_t*)g_x)[i*2+0] = cvt_f16x2(v.x, v.y);
    ((uint32_t*)g_x)[i*2+1] = cvt_f16x2(v.z, v.w);
}
__global__ __launch_bounds__(256) void conv_wt_kernel(const float* __restrict__ W0,
                                                      const float* __restrict__ W1,
                                                      const float* __restrict__ W2,
                                                      const float* __restrict__ W3) {
    __shared__ float tile[32][33];
    const int z = blockIdx.z;
    const float* W = (z == 0) ? W0 : (z == 1) ? W1 : (z == 2) ? W2 : W3;
    const int n0 = blockIdx.x * 32, k0 = blockIdx.y * 32;
    const int tx = threadIdx.x, ty = threadIdx.y;
#pragma unroll
    for (int i = ty; i < 32; i += 8)
        tile[i][tx] = W[(size_t)(k0 + i) * DM + n0 + tx];
    __syncthreads();
#pragma unroll
    for (int i = ty; i < 32; i += 8)
        g_wf[z][(size_t)(n0 + i) * DM + k0 + tx] = __float2half_rn(tile[tx][i]);
}

// ---- Flash attention: 4 warps x 32 query rows, K/V frags shared across m-frags ---
__global__ __launch_bounds__(ATHREADS, 2)
void attn_kernel(const unsigned char* __restrict__ pad)
{
    extern __shared__ char smem[];
    const uint32_t sb = smem_to_u32(smem);
    const int tid = threadIdx.x, lane = tid & 31, wq = tid >> 5;   // wq 0..3
    const int b = blockIdx.y >> 4, h = blockIdx.y & 15;
    const int bx = (gridDim.x - 1) - blockIdx.x;   // heavy blocks first
    const int qbase = bx * 128;
    const int ntiles = bx * 2 + 2;

    // Q load (128 rows) — bundled into commit group 0
    {
        const __half* srcq = g_q + (size_t)(b * SEQ + qbase) * DM + h * HD;
#pragma unroll
        for (int i = 0; i < 8; i++) {
            int q = tid + i * ATHREADS;
            int row = q >> 3, ch = q & 7;
            cpasync16(sb + AOFF_Q + (row * APITCH + ch * 8) * 2,
                      srcq + (size_t)row * DM + ch * 8);
        }
    }

    auto issue = [&](int t) {
        if (t < ntiles) {
            const int k0 = t * 64;
            const uint32_t sbase = sb + AOFF_ST + (t % ASTAGES) * ASTG_B;
            const __half* gs[2] = {
                g_k + (size_t)(b * SEQ + k0) * DM + h * HD,
                g_v + (size_t)(b * SEQ + k0) * DM + h * HD };
#pragma unroll
            for (int i = 0; i < 8; i++) {
                int q = tid + i * ATHREADS;
                int tt = q >> 9, row = (q >> 3) & 63, ch = q & 7;
                cpasync16(sbase + tt * AK_B + (row * APITCH + ch * 8) * 2,
                          gs[tt] + (size_t)row * DM + ch * 8);
            }
        }
        asm volatile("cp.async.commit_group;");
    };
    auto pmload = [&](int t) {
        if (t < ntiles && tid < 64) {
            float v = pad[b * SEQ + t * 64 + tid] ? -CUDART_INF_F : 0.f;
            *(float*)(smem + AOFF_PM + (t % ASTAGES) * 256 + tid * 4) = v;
        }
    };

    pmload(0); issue(0);
    pmload(1); issue(1);

    const int r  = lane >> 2;
    const int c2 = (lane & 3) * 2;
    const int wrow = qbase + wq * 32;           // warp's first query row
    const int qmax = wrow + 31;

    const int a_r = (lane & 7) + ((lane >> 3) & 1) * 8;
    const int a_c = (lane >> 4) * 8;
    const int b_r = (lane & 7) + ((lane >> 4) & 1) * 8;
    const int b_c = ((lane >> 3) & 1) * 8;
    const int v_r = (lane & 7) + ((lane >> 3) & 1) * 8;
    const int v_c = (lane >> 4) * 8;

    // per m-frag state: mf 0 -> rows wrow+r / wrow+r+8; mf 1 -> +16 / +24
    float m[2][2], l[2][2];
#pragma unroll
    for (int mf = 0; mf < 2; mf++) {
        m[mf][0] = m[mf][1] = -CUDART_INF_F;
        l[mf][0] = l[mf][1] = 0.f;
    }
    float o[2][8][4];
#pragma unroll
    for (int mf = 0; mf < 2; mf++)
#pragma unroll
        for (int i = 0; i < 8; i++)
#pragma unroll
            for (int j = 0; j < 4; j++) o[mf][i][j] = 0.f;

    uint32_t qf[2][4][4];

    for (int t = 0; t < ntiles; t++) {
        asm volatile("cp.async.wait_group %0;" :: "n"(1));
        __syncthreads();

        if (t == 0) {
#pragma unroll
            for (int mf = 0; mf < 2; mf++)
#pragma unroll
                for (int dk = 0; dk < 4; dk++)
                    ldsm_x4(qf[mf][dk],
                            sb + AOFF_Q + ((wq * 32 + mf * 16 + a_r) * APITCH + dk * 16 + a_c) * 2);
        }
        pmload(t + 2);
        issue(t + 2);

        const int k0 = t * 64;
        if (k0 <= qmax) {
            const uint32_t st = sb + AOFF_ST + (t % ASTAGES) * ASTG_B;
            // ---- S = Q K^T; K frags loaded once, used by both m-frags ----
            float s[2][8][4];
#pragma unroll
            for (int mf = 0; mf < 2; mf++)
#pragma unroll
                for (int f = 0; f < 8; f++)
#pragma unroll
                    for (int j = 0; j < 4; j++) s[mf][f][j] = 0.f;

#pragma unroll
            for (int dk = 0; dk < 4; dk++) {
                uint32_t kf[4][4];
#pragma unroll
                for (int g = 0; g < 4; g++)
                    ldsm_x4(kf[g], st + ((g * 16 + b_r) * APITCH + dk * 16 + b_c) * 2);
#pragma unroll
                for (int mf = 0; mf < 2; mf++)
#pragma unroll
                    for (int f = 0; f < 8; f++)
                        mma_f16(s[mf][f], qf[mf][dk], &kf[f >> 1][(f & 1) * 2]);
            }

            // ---- masks + softmax per m-frag ----
            uint32_t pah[2][4][4];
#pragma unroll
            for (int mf = 0; mf < 2; mf++) {
                const int row0 = wrow + mf * 16 + r;
                const int row1 = row0 + 8;
                const bool needc = (k0 + 63 > row0);
#pragma unroll
                for (int f = 0; f < 8; f++) {
                    float2 pmv = *(float2*)(smem + AOFF_PM + (t % ASTAGES) * 256 + (f * 8 + c2) * 4);
                    s[mf][f][0] += pmv.x; s[mf][f][1] += pmv.y;
                    s[mf][f][2] += pmv.x; s[mf][f][3] += pmv.y;
                    if (needc) {
                        int k = k0 + f * 8 + c2;
                        if (k     > row0) s[mf][f][0] = -CUDART_INF_F;
                        if (k + 1 > row0) s[mf][f][1] = -CUDART_INF_F;
                        if (k     > row1) s[mf][f][2] = -CUDART_INF_F;
                        if (k + 1 > row1) s[mf][f][3] = -CUDART_INF_F;
                    }
                }

                float mx0 = -CUDART_INF_F, mx1 = -CUDART_INF_F;
#pragma unroll
                for (int f = 0; f < 8; f++) {
                    mx0 = fmaxf(mx0, fmaxf(s[mf][f][0], s[mf][f][1]));
                    mx1 = fmaxf(mx1, fmaxf(s[mf][f][2], s[mf][f][3]));
                }
                mx0 = fmaxf(mx0, __shfl_xor_sync(0xffffffff, mx0, 1));
                mx0 = fmaxf(mx0, __shfl_xor_sync(0xffffffff, mx0, 2));
                mx1 = fmaxf(mx1, __shfl_xor_sync(0xffffffff, mx1, 1));
                mx1 = fmaxf(mx1, __shfl_xor_sync(0xffffffff, mx1, 2));
                const float mn0 = fmaxf(m[mf][0], mx0), mn1 = fmaxf(m[mf][1], mx1);
                const float al0 = exp2f(m[mf][0] - mn0), al1 = exp2f(m[mf][1] - mn1);
                m[mf][0] = mn0; m[mf][1] = mn1;

                float rs0 = 0.f, rs1 = 0.f;
#pragma unroll
                for (int f = 0; f < 8; f++) {
                    float p0 = exp2f(s[mf][f][0] - mn0), p1 = exp2f(s[mf][f][1] - mn0);
                    float p2 = exp2f(s[mf][f][2] - mn1), p3 = exp2f(s[mf][f][3] - mn1);
                    rs0 += p0 + p1; rs1 += p2 + p3;
                    const int ks = f >> 1, hi = (f & 1) * 2;
                    pah[mf][ks][hi]     = cvt_f16x2(p0, p1);
                    pah[mf][ks][hi + 1] = cvt_f16x2(p2, p3);
                }
                rs0 += __shfl_xor_sync(0xffffffff, rs0, 1);
                rs0 += __shfl_xor_sync(0xffffffff, rs0, 2);
                rs1 += __shfl_xor_sync(0xffffffff, rs1, 1);
                rs1 += __shfl_xor_sync(0xffffffff, rs1, 2);
                l[mf][0] = l[mf][0] * al0 + rs0;
                l[mf][1] = l[mf][1] * al1 + rs1;

#pragma unroll
                for (int nd = 0; nd < 8; nd++) {
                    o[mf][nd][0] *= al0; o[mf][nd][1] *= al0;
                    o[mf][nd][2] *= al1; o[mf][nd][3] *= al1;
                }
            }

            // ---- O += P V; V frags loaded once, used by both m-frags ----
#pragma unroll
            for (int ks = 0; ks < 4; ks++) {
                uint32_t vf[4][4];
#pragma unroll
                for (int g = 0; g < 4; g++)
                    ldsm_x4_t(vf[g], st + AK_B + ((ks * 16 + v_r) * APITCH + g * 16 + v_c) * 2);
#pragma unroll
                for (int mf = 0; mf < 2; mf++)
#pragma unroll
                    for (int nd = 0; nd < 8; nd++)
                        mma_f16(o[mf][nd], pah[mf][ks], &vf[nd >> 1][(nd & 1) * 2]);
            }
        }
    }

    // ---- epilogue ----
#pragma unroll
    for (int mf = 0; mf < 2; mf++) {
        const int row0 = wrow + mf * 16 + r;
        const float inv0 = (l[mf][0] > 0.f) ? (1.f / l[mf][0]) : 0.f;
        const float inv1 = (l[mf][1] > 0.f) ? (1.f / l[mf][1]) : 0.f;
        const size_t r0off = (size_t)(b * SEQ + row0) * DM + h * HD;
        const size_t r1off = (size_t)(b * SEQ + row0 + 8) * DM + h * HD;
#pragma unroll
        for (int nd = 0; nd < 8; nd++) {
            const int col = nd * 8 + c2;
            *(uint32_t*)&g_a[r0off + col] = cvt_f16x2(o[mf][nd][0] * inv0, o[mf][nd][1] * inv0);
            *(uint32_t*)&g_a[r1off + col] = cvt_f16x2(o[mf][nd][2] * inv1, o[mf][nd][3] * inv1);
        }
    }
}

// ---- Launch ------------------------------------------------------------------------
extern "C" void kernel_launch(void* const* d_in, const int* in_sizes, int n_in,
                              void* d_out, int out_size)
{
    (void)in_sizes; (void)n_in; (void)out_size;
    const float*         x   = (const float*)d_in[0];
    const unsigned char* pad = (const unsigned char*)d_in[1];
    const float*         Wq  = (const float*)d_in[2];
    const float*         Wk  = (const float*)d_in[3];
    const float*         Wv  = (const float*)d_in[4];
    const float*         Wo  = (const float*)d_in[5];
    float*               out = (float*)d_out;

    cudaFuncSetAttribute(qkv_mma_kernel, cudaFuncAttributeMaxDynamicSharedMemorySize, GEMM_SMEM);
    cudaFuncSetAttribute(out_mma_kernel, cudaFuncAttributeMaxDynamicSharedMemorySize, GEMM_SMEM);
    cudaFuncSetAttribute(attn_kernel, cudaFuncAttributeMaxDynamicSharedMemorySize, ATTN_SMEM);

    conv_x_kernel<<<MROWS * DM / 4 / 256, 256>>>(x);
    conv_wt_kernel<<<dim3(DM / 32, DM / 32, 4), dim3(32, 8)>>>(Wq, Wk, Wv, Wo);

    qkv_mma_kernel<<<dim3(DM / BN, MROWS / BM, 3), 256, GEMM_SMEM>>>();

    attn_kernel<<<dim3(SEQ / 128, BATCH * NH), ATHREADS, ATTN_SMEM>>>(pad);

    out_mma_kernel<<<dim3(DM / BN, MROWS / BM), 256, GEMM_SMEM>>>(out);
}

// round 13
// speedup vs baseline: 1.0785x; 1.0785x over previous
#include <cuda_runtime.h>
#include <cuda_bf16.h>
#include <cuda_fp16.h>
#include <math_constants.h>
#include <cstdint>

// ---------------------------------------------------------------------------
// MHA Round 13: attention reverted to R11 config (8 warps x 16 rows, 256 thr,
// 2 CTAs/SM). GEMMs: BK 32->64, 3-stage ring, pitch 72 -> half the barriers.
// ---------------------------------------------------------------------------

#define BATCH 4
#define SEQ   2048
#define DM    1024
#define NH    16
#define HD    64
#define MROWS (BATCH * SEQ)
#define ATT_SCALE 0.125f
#define LOG2E 1.44269504088896340736f

// GEMM tiling: 128x128 block, BK=64 chunks
#define BM 128
#define BN 128
#define GBK 64
#define GNCH (DM / GBK)                     // 16
#define GSTAGES 3
#define GPITCH 72                           // 64 data + 8 pad bf16 elems
#define GTILE_B (128 * GPITCH * 2)          // 18432
#define GSTAGE_B (2 * GTILE_B)              // 36864
#define GEMM_SMEM (GSTAGES * GSTAGE_B)      // 110592

// attention smem (R11 layout)
#define APITCH 72
#define AQ_B   (128 * APITCH * 2)           // 18432 (single Q)
#define AK_B   (64 * APITCH * 2)            // 9216 per K/V tile
#define ASTG_B (2 * AK_B)                   // 18432 per stage (K, V)
#define ASTAGES 3
#define AOFF_Q  0
#define AOFF_ST AQ_B                          // 18432
#define AOFF_PM (AOFF_ST + ASTAGES * ASTG_B)  // 73728
#define ATTN_SMEM (AOFF_PM + 768)             // 74496

// ---- scratch ----------------------------------------------------------------
__device__ __align__(256) __half g_x [MROWS * DM];
__device__ __align__(256) __half g_q [MROWS * DM];
__device__ __align__(256) __half g_k [MROWS * DM];
__device__ __align__(256) __half g_v [MROWS * DM];
__device__ __align__(256) __half g_a [MROWS * DM];
__device__ __align__(256) __half g_wf[4][DM * DM];        // W^T fp16: q,k,v,o

// ---- helpers ------------------------------------------------------------------
__device__ __forceinline__ uint32_t smem_to_u32(const void* p) {
    uint32_t a;
    asm("{ .reg .u64 t; cvta.to.shared.u64 t, %1; cvt.u32.u64 %0, t; }"
        : "=r"(a) : "l"(p));
    return a;
}
__device__ __forceinline__ void mma_f16(float* d, const uint32_t* a, const uint32_t* b) {
    asm volatile(
        "mma.sync.aligned.m16n8k16.row.col.f32.f16.f16.f32 "
        "{%0,%1,%2,%3}, {%4,%5,%6,%7}, {%8,%9}, {%0,%1,%2,%3};\n"
        : "+f"(d[0]), "+f"(d[1]), "+f"(d[2]), "+f"(d[3])
        : "r"(a[0]), "r"(a[1]), "r"(a[2]), "r"(a[3]), "r"(b[0]), "r"(b[1]));
}
__device__ __forceinline__ void ldsm_x4(uint32_t* r, uint32_t addr) {
    asm volatile("ldmatrix.sync.aligned.m8n8.x4.shared.b16 {%0,%1,%2,%3}, [%4];"
        : "=r"(r[0]), "=r"(r[1]), "=r"(r[2]), "=r"(r[3]) : "r"(addr));
}
__device__ __forceinline__ void ldsm_x4_t(uint32_t* r, uint32_t addr) {
    asm volatile("ldmatrix.sync.aligned.m8n8.x4.trans.shared.b16 {%0,%1,%2,%3}, [%4];"
        : "=r"(r[0]), "=r"(r[1]), "=r"(r[2]), "=r"(r[3]) : "r"(addr));
}
__device__ __forceinline__ void cpasync16(uint32_t dst, const void* src) {
    asm volatile("cp.async.cg.shared.global [%0], [%1], 16;" :: "r"(dst), "l"(src));
}
__device__ __forceinline__ uint32_t pack_h2(__half a, __half b) {
    __half2 t = __halves2half2(a, b);
    return *(uint32_t*)&t;
}
__device__ __forceinline__ uint32_t cvt_f16x2(float f_lo, float f_hi) {
    uint32_t r;
    asm("cvt.rn.f16x2.f32 %0, %1, %2;" : "=r"(r) : "f"(f_hi), "f"(f_lo));
    return r;
}

// ---- GEMM body: single-pass fp16, BK=64, 3-stage ring -----------------------------
// OMODE: 0 fp32 C; 2 single-fp16 (Ch) scaled.
template<int OMODE>
__device__ __forceinline__ void gemm_body(
    const __half* A_, const __half* B_,
    float* __restrict__ C, __half* __restrict__ Ch, float scale)
{
    extern __shared__ char smem[];
    const uint32_t sb = smem_to_u32(smem);
    const int tid  = threadIdx.x;
    const int lane = tid & 31;
    const int wid  = tid >> 5;
    const int wm   = wid >> 2;
    const int wn   = wid & 3;
    const int bm = blockIdx.y, bn = blockIdx.x;

    const __half* gsrc[2] = {
        A_ + (size_t)bm * BM * DM,
        B_ + (size_t)bn * BN * DM
    };

    float acc[4][4][4];
#pragma unroll
    for (int i = 0; i < 4; i++)
#pragma unroll
        for (int j = 0; j < 4; j++)
#pragma unroll
            for (int r = 0; r < 4; r++) acc[i][j][r] = 0.f;

    auto issue = [&](int c) {
        if (c < GNCH) {
            const uint32_t sbase = sb + (c % GSTAGES) * GSTAGE_B;
            const size_t koff = (size_t)c * GBK;
#pragma unroll
            for (int i = 0; i < 8; i++) {
                int q = tid + i * 256;
                int t = q >> 10, r = (q >> 3) & 127, ch = q & 7;
                cpasync16(sbase + t * GTILE_B + (r * GPITCH + ch * 8) * 2,
                          gsrc[t] + (size_t)r * DM + koff + ch * 8);
            }
        }
        asm volatile("cp.async.commit_group;");
    };

    issue(0); issue(1);

    const int a_r = (lane & 7) + ((lane >> 3) & 1) * 8;
    const int a_c = (lane >> 4) * 8;
    const int b_r = (lane & 7) + ((lane >> 4) & 1) * 8;
    const int b_c = ((lane >> 3) & 1) * 8;

    for (int c = 0; c < GNCH; c++) {
        asm volatile("cp.async.wait_group %0;" :: "n"(1));
        __syncthreads();
        issue(c + 2);   // refills ring slot (c-1)%3, fully consumed before this barrier

        const uint32_t st = sb + (c % GSTAGES) * GSTAGE_B;
        const uint32_t sA = st, sB = st + GTILE_B;

#pragma unroll
        for (int k16 = 0; k16 < 4; k16++) {
            const int kc = k16 * 16;
            uint32_t ah[4][4], bh[2][4];
#pragma unroll
            for (int mfi = 0; mfi < 4; mfi++)
                ldsm_x4(ah[mfi], sA + ((wm * 64 + mfi * 16 + a_r) * GPITCH + kc + a_c) * 2);
#pragma unroll
            for (int nfp = 0; nfp < 2; nfp++)
                ldsm_x4(bh[nfp], sB + ((wn * 32 + nfp * 16 + b_r) * GPITCH + kc + b_c) * 2);
#pragma unroll
            for (int mfi = 0; mfi < 4; mfi++)
#pragma unroll
                for (int nf = 0; nf < 4; nf++)
                    mma_f16(acc[mfi][nf], ah[mfi], &bh[nf >> 1][(nf & 1) * 2]);
        }
    }

#pragma unroll
    for (int mfi = 0; mfi < 4; mfi++)
#pragma unroll
        for (int nf = 0; nf < 4; nf++) {
            int row = bm * BM + wm * 64 + mfi * 16 + (lane >> 2);
            int col = bn * BN + wn * 32 + nf * 8 + (lane & 3) * 2;
            float v0 = acc[mfi][nf][0] * scale, v1 = acc[mfi][nf][1] * scale;
            float v2 = acc[mfi][nf][2] * scale, v3 = acc[mfi][nf][3] * scale;
            if (OMODE == 0) {
                *(float2*)&C[(size_t)row * DM + col]       = make_float2(v0, v1);
                *(float2*)&C[(size_t)(row + 8) * DM + col] = make_float2(v2, v3);
            } else {
                *(uint32_t*)&Ch[(size_t)row * DM + col]       = cvt_f16x2(v0, v1);
                *(uint32_t*)&Ch[(size_t)(row + 8) * DM + col] = cvt_f16x2(v2, v3);
            }
        }
}

__global__ __launch_bounds__(256, 2)
void qkv_mma_kernel()
{
    const int z = blockIdx.z;
    if (z == 0)
        gemm_body<2>(g_x, g_wf[0], nullptr, g_q, ATT_SCALE * LOG2E);
    else if (z == 1)
        gemm_body<2>(g_x, g_wf[1], nullptr, g_k, 1.f);
    else
        gemm_body<2>(g_x, g_wf[2], nullptr, g_v, 1.f);
}
__global__ __launch_bounds__(256, 2)
void out_mma_kernel(float* __restrict__ out)
{
    gemm_body<0>(g_a, g_wf[3], out, nullptr, 1.f);
}

// ---- conversions --------------------------------------------------------------
__global__ __launch_bounds__(256) void conv_x_kernel(const float* __restrict__ s) {
    int i = blockIdx.x * 256 + threadIdx.x;
    float4 v = ((const float4*)s)[i];
    ((uint32_t*)g_x)[i*2+0] = cvt_f16x2(v.x, v.y);
    ((uint32_t*)g_x)[i*2+1] = cvt_f16x2(v.z, v.w);
}
__global__ __launch_bounds__(256) void conv_wt_kernel(const float* __restrict__ W0,
                                                      const float* __restrict__ W1,
                                                      const float* __restrict__ W2,
                                                      const float* __restrict__ W3) {
    __shared__ float tile[32][33];
    const int z = blockIdx.z;
    const float* W = (z == 0) ? W0 : (z == 1) ? W1 : (z == 2) ? W2 : W3;
    const int n0 = blockIdx.x * 32, k0 = blockIdx.y * 32;
    const int tx = threadIdx.x, ty = threadIdx.y;
#pragma unroll
    for (int i = ty; i < 32; i += 8)
        tile[i][tx] = W[(size_t)(k0 + i) * DM + n0 + tx];
    __syncthreads();
#pragma unroll
    for (int i = ty; i < 32; i += 8)
        g_wf[z][(size_t)(n0 + i) * DM + k0 + tx] = __float2half_rn(tile[tx][i]);
}

// ---- Flash attention (R11 config: 8 warps x 16 rows, 256 threads) -----------------
__global__ __launch_bounds__(256, 2)
void attn_kernel(const unsigned char* __restrict__ pad)
{
    extern __shared__ char smem[];
    const uint32_t sb = smem_to_u32(smem);
    const int tid = threadIdx.x, lane = tid & 31, wq = tid >> 5;
    const int b = blockIdx.y >> 4, h = blockIdx.y & 15;
    const int bx = (gridDim.x - 1) - blockIdx.x;   // heavy blocks first
    const int qbase = bx * 128;
    const int ntiles = bx * 2 + 2;

    // Q load (single operand) — bundled into commit group 0
    {
        const __half* srcq = g_q + (size_t)(b * SEQ + qbase) * DM + h * HD;
#pragma unroll
        for (int i = 0; i < 4; i++) {
            int q = tid + i * 256;
            int row = q >> 3, ch = q & 7;
            cpasync16(sb + AOFF_Q + (row * APITCH + ch * 8) * 2,
                      srcq + (size_t)row * DM + ch * 8);
        }
    }

    auto issue = [&](int t) {
        if (t < ntiles) {
            const int k0 = t * 64;
            const uint32_t sbase = sb + AOFF_ST + (t % ASTAGES) * ASTG_B;
            const __half* gs[2] = {
                g_k + (size_t)(b * SEQ + k0) * DM + h * HD,
                g_v + (size_t)(b * SEQ + k0) * DM + h * HD };
#pragma unroll
            for (int i = 0; i < 4; i++) {
                int q = tid + i * 256;
                int tt = q >> 9, row = (q >> 3) & 63, ch = q & 7;
                cpasync16(sbase + tt * AK_B + (row * APITCH + ch * 8) * 2,
                          gs[tt] + (size_t)row * DM + ch * 8);
            }
        }
        asm volatile("cp.async.commit_group;");
    };
    auto pmload = [&](int t) {
        if (t < ntiles && tid < 64) {
            float v = pad[b * SEQ + t * 64 + tid] ? -CUDART_INF_F : 0.f;
            *(float*)(smem + AOFF_PM + (t % ASTAGES) * 256 + tid * 4) = v;
        }
    };

    pmload(0); issue(0);
    pmload(1); issue(1);

    const int r  = lane >> 2;
    const int c2 = (lane & 3) * 2;
    const int row0 = qbase + wq * 16 + r;
    const int row1 = row0 + 8;
    const int qmax = qbase + wq * 16 + 15;

    const int a_r = (lane & 7) + ((lane >> 3) & 1) * 8;
    const int a_c = (lane >> 4) * 8;
    const int b_r = (lane & 7) + ((lane >> 4) & 1) * 8;
    const int b_c = ((lane >> 3) & 1) * 8;
    const int v_r = (lane & 7) + ((lane >> 3) & 1) * 8;
    const int v_c = (lane >> 4) * 8;

    float m0 = -CUDART_INF_F, m1 = -CUDART_INF_F, l0 = 0.f, l1 = 0.f;
    float o[8][4];
#pragma unroll
    for (int i = 0; i < 8; i++)
#pragma unroll
        for (int j = 0; j < 4; j++) o[i][j] = 0.f;

    uint32_t qf[4][4];

    for (int t = 0; t < ntiles; t++) {
        asm volatile("cp.async.wait_group %0;" :: "n"(1));
        __syncthreads();

        if (t == 0) {
#pragma unroll
            for (int dk = 0; dk < 4; dk++)
                ldsm_x4(qf[dk], sb + AOFF_Q + ((wq * 16 + a_r) * APITCH + dk * 16 + a_c) * 2);
        }
        pmload(t + 2);
        issue(t + 2);

        const int k0 = t * 64;
        if (k0 <= qmax) {
            const uint32_t st = sb + AOFF_ST + (t % ASTAGES) * ASTG_B;
            // ---- S = Q K^T, single-pass fp16 ----
            float s[8][4];
#pragma unroll
            for (int f = 0; f < 8; f++)
#pragma unroll
                for (int j = 0; j < 4; j++) s[f][j] = 0.f;

#pragma unroll
            for (int dk = 0; dk < 4; dk++) {
                uint32_t kf[4][4];
#pragma unroll
                for (int g = 0; g < 4; g++)
                    ldsm_x4(kf[g], st + ((g * 16 + b_r) * APITCH + dk * 16 + b_c) * 2);
#pragma unroll
                for (int f = 0; f < 8; f++)
                    mma_f16(s[f], qf[dk], &kf[f >> 1][(f & 1) * 2]);
            }

            // ---- masks ----
            const bool needc = (k0 + 63 > row0);
#pragma unroll
            for (int f = 0; f < 8; f++) {
                float2 pmv = *(float2*)(smem + AOFF_PM + (t % ASTAGES) * 256 + (f * 8 + c2) * 4);
                s[f][0] += pmv.x; s[f][1] += pmv.y;
                s[f][2] += pmv.x; s[f][3] += pmv.y;
                if (needc) {
                    int k = k0 + f * 8 + c2;
                    if (k     > row0) s[f][0] = -CUDART_INF_F;
                    if (k + 1 > row0) s[f][1] = -CUDART_INF_F;
                    if (k     > row1) s[f][2] = -CUDART_INF_F;
                    if (k + 1 > row1) s[f][3] = -CUDART_INF_F;
                }
            }

            // ---- online softmax (base 2) ----
            float mx0 = -CUDART_INF_F, mx1 = -CUDART_INF_F;
#pragma unroll
            for (int f = 0; f < 8; f++) {
                mx0 = fmaxf(mx0, fmaxf(s[f][0], s[f][1]));
                mx1 = fmaxf(mx1, fmaxf(s[f][2], s[f][3]));
            }
            mx0 = fmaxf(mx0, __shfl_xor_sync(0xffffffff, mx0, 1));
            mx0 = fmaxf(mx0, __shfl_xor_sync(0xffffffff, mx0, 2));
            mx1 = fmaxf(mx1, __shfl_xor_sync(0xffffffff, mx1, 1));
            mx1 = fmaxf(mx1, __shfl_xor_sync(0xffffffff, mx1, 2));
            const float mn0 = fmaxf(m0, mx0), mn1 = fmaxf(m1, mx1);
            const float al0 = exp2f(m0 - mn0), al1 = exp2f(m1 - mn1);
            m0 = mn0; m1 = mn1;

            uint32_t pah[4][4];
            float rs0 = 0.f, rs1 = 0.f;
#pragma unroll
            for (int f = 0; f < 8; f++) {
                float p0 = exp2f(s[f][0] - mn0), p1 = exp2f(s[f][1] - mn0);
                float p2 = exp2f(s[f][2] - mn1), p3 = exp2f(s[f][3] - mn1);
                rs0 += p0 + p1; rs1 += p2 + p3;
                const int ks = f >> 1, hi = (f & 1) * 2;
                pah[ks][hi]     = cvt_f16x2(p0, p1);
                pah[ks][hi + 1] = cvt_f16x2(p2, p3);
            }
            rs0 += __shfl_xor_sync(0xffffffff, rs0, 1);
            rs0 += __shfl_xor_sync(0xffffffff, rs0, 2);
            rs1 += __shfl_xor_sync(0xffffffff, rs1, 1);
            rs1 += __shfl_xor_sync(0xffffffff, rs1, 2);
            l0 = l0 * al0 + rs0;
            l1 = l1 * al1 + rs1;

#pragma unroll
            for (int nd = 0; nd < 8; nd++) {
                o[nd][0] *= al0; o[nd][1] *= al0;
                o[nd][2] *= al1; o[nd][3] *= al1;
            }

            // ---- O += P V, single-pass fp16 ----
#pragma unroll
            for (int ks = 0; ks < 4; ks++) {
                uint32_t vf[4][4];
#pragma unroll
                for (int g = 0; g < 4; g++)
                    ldsm_x4_t(vf[g], st + AK_B + ((ks * 16 + v_r) * APITCH + g * 16 + v_c) * 2);
#pragma unroll
                for (int nd = 0; nd < 8; nd++)
                    mma_f16(o[nd], pah[ks], &vf[nd >> 1][(nd & 1) * 2]);
            }
        }
    }

    // ---- epilogue: O/l -> single fp16 into g_a ----
    const float inv0 = (l0 > 0.f) ? (1.f / l0) : 0.f;
    const float inv1 = (l1 > 0.f) ? (1.f / l1) : 0.f;
    const size_t r0off = (size_t)(b * SEQ + row0) * DM + h * HD;
    const size_t r1off = (size_t)(b * SEQ + row1) * DM + h * HD;
#pragma unroll
    for (int nd = 0; nd < 8; nd++) {
        const int col = nd * 8 + c2;
        *(uint32_t*)&g_a[r0off + col] = cvt_f16x2(o[nd][0] * inv0, o[nd][1] * inv0);
        *(uint32_t*)&g_a[r1off + col] = cvt_f16x2(o[nd][2] * inv1, o[nd][3] * inv1);
    }
}

// ---- Launch ------------------------------------------------------------------------
extern "C" void kernel_launch(void* const* d_in, const int* in_sizes, int n_in,
                              void* d_out, int out_size)
{
    (void)in_sizes; (void)n_in; (void)out_size;
    const float*         x   = (const float*)d_in[0];
    const unsigned char* pad = (const unsigned char*)d_in[1];
    const float*         Wq  = (const float*)d_in[2];
    const float*         Wk  = (const float*)d_in[3];
    const float*         Wv  = (const float*)d_in[4];
    const float*         Wo  = (const float*)d_in[5];
    float*               out = (float*)d_out;

    cudaFuncSetAttribute(qkv_mma_kernel, cudaFuncAttributeMaxDynamicSharedMemorySize, GEMM_SMEM);
    cudaFuncSetAttribute(out_mma_kernel, cudaFuncAttributeMaxDynamicSharedMemorySize, GEMM_SMEM);
    cudaFuncSetAttribute(attn_kernel, cudaFuncAttributeMaxDynamicSharedMemorySize, ATTN_SMEM);

    conv_x_kernel<<<MROWS * DM / 4 / 256, 256>>>(x);
    conv_wt_kernel<<<dim3(DM / 32, DM / 32, 4), dim3(32, 8)>>>(Wq, Wk, Wv, Wo);

    qkv_mma_kernel<<<dim3(DM / BN, MROWS / BM, 3), 256, GEMM_SMEM>>>();

    attn_kernel<<<dim3(SEQ / 128, BATCH * NH), 256, ATTN_SMEM>>>(pad);

    out_mma_kernel<<<dim3(DM / BN, MROWS / BM), 256, GEMM_SMEM>>>(out);
}

// round 14
// speedup vs baseline: 1.1158x; 1.0346x over previous
#include <cuda_runtime.h>
#include <cuda_bf16.h>
#include <cuda_fp16.h>
#include <math_constants.h>
#include <cstdint>

// ---------------------------------------------------------------------------
// MHA Round 14: attention softmax-overhead cuts.
//  - pad-flag skip: ballot pad bytes -> per-stage flag; mask adds only if set
//  - deferred l-reduction: per-lane partials, one shfl-reduce in epilogue
//  - K/V ring 3->4 stages, wait_group(2)
// GEMMs unchanged from R13 (BK=64, 3-stage, 2 CTAs/SM).
// ---------------------------------------------------------------------------

#define BATCH 4
#define SEQ   2048
#define DM    1024
#define NH    16
#define HD    64
#define MROWS (BATCH * SEQ)
#define ATT_SCALE 0.125f
#define LOG2E 1.44269504088896340736f

// GEMM tiling: 128x128 block, BK=64 chunks
#define BM 128
#define BN 128
#define GBK 64
#define GNCH (DM / GBK)                     // 16
#define GSTAGES 3
#define GPITCH 72
#define GTILE_B (128 * GPITCH * 2)          // 18432
#define GSTAGE_B (2 * GTILE_B)              // 36864
#define GEMM_SMEM (GSTAGES * GSTAGE_B)      // 110592

// attention smem
#define APITCH 72
#define AQ_B   (128 * APITCH * 2)           // 18432 (single Q)
#define AK_B   (64 * APITCH * 2)            // 9216 per K/V tile
#define ASTG_B (2 * AK_B)                   // 18432 per stage (K, V)
#define ASTAGES 4
#define APM_STRIDE 320                      // 256B pm values + flag words
#define AOFF_Q  0
#define AOFF_ST AQ_B                          // 18432
#define AOFF_PM (AOFF_ST + ASTAGES * ASTG_B)  // 92160
#define ATTN_SMEM (AOFF_PM + ASTAGES * APM_STRIDE)  // 93440

// ---- scratch ----------------------------------------------------------------
__device__ __align__(256) __half g_x [MROWS * DM];
__device__ __align__(256) __half g_q [MROWS * DM];
__device__ __align__(256) __half g_k [MROWS * DM];
__device__ __align__(256) __half g_v [MROWS * DM];
__device__ __align__(256) __half g_a [MROWS * DM];
__device__ __align__(256) __half g_wf[4][DM * DM];        // W^T fp16: q,k,v,o

// ---- helpers ------------------------------------------------------------------
__device__ __forceinline__ uint32_t smem_to_u32(const void* p) {
    uint32_t a;
    asm("{ .reg .u64 t; cvta.to.shared.u64 t, %1; cvt.u32.u64 %0, t; }"
        : "=r"(a) : "l"(p));
    return a;
}
__device__ __forceinline__ void mma_f16(float* d, const uint32_t* a, const uint32_t* b) {
    asm volatile(
        "mma.sync.aligned.m16n8k16.row.col.f32.f16.f16.f32 "
        "{%0,%1,%2,%3}, {%4,%5,%6,%7}, {%8,%9}, {%0,%1,%2,%3};\n"
        : "+f"(d[0]), "+f"(d[1]), "+f"(d[2]), "+f"(d[3])
        : "r"(a[0]), "r"(a[1]), "r"(a[2]), "r"(a[3]), "r"(b[0]), "r"(b[1]));
}
__device__ __forceinline__ void ldsm_x4(uint32_t* r, uint32_t addr) {
    asm volatile("ldmatrix.sync.aligned.m8n8.x4.shared.b16 {%0,%1,%2,%3}, [%4];"
        : "=r"(r[0]), "=r"(r[1]), "=r"(r[2]), "=r"(r[3]) : "r"(addr));
}
__device__ __forceinline__ void ldsm_x4_t(uint32_t* r, uint32_t addr) {
    asm volatile("ldmatrix.sync.aligned.m8n8.x4.trans.shared.b16 {%0,%1,%2,%3}, [%4];"
        : "=r"(r[0]), "=r"(r[1]), "=r"(r[2]), "=r"(r[3]) : "r"(addr));
}
__device__ __forceinline__ void cpasync16(uint32_t dst, const void* src) {
    asm volatile("cp.async.cg.shared.global [%0], [%1], 16;" :: "r"(dst), "l"(src));
}
__device__ __forceinline__ uint32_t cvt_f16x2(float f_lo, float f_hi) {
    uint32_t r;
    asm("cvt.rn.f16x2.f32 %0, %1, %2;" : "=r"(r) : "f"(f_hi), "f"(f_lo));
    return r;
}

// ---- GEMM body: single-pass fp16, BK=64, 3-stage ring (unchanged from R13) -------
template<int OMODE>
__device__ __forceinline__ void gemm_body(
    const __half* A_, const __half* B_,
    float* __restrict__ C, __half* __restrict__ Ch, float scale)
{
    extern __shared__ char smem[];
    const uint32_t sb = smem_to_u32(smem);
    const int tid  = threadIdx.x;
    const int lane = tid & 31;
    const int wid  = tid >> 5;
    const int wm   = wid >> 2;
    const int wn   = wid & 3;
    const int bm = blockIdx.y, bn = blockIdx.x;

    const __half* gsrc[2] = {
        A_ + (size_t)bm * BM * DM,
        B_ + (size_t)bn * BN * DM
    };

    float acc[4][4][4];
#pragma unroll
    for (int i = 0; i < 4; i++)
#pragma unroll
        for (int j = 0; j < 4; j++)
#pragma unroll
            for (int r = 0; r < 4; r++) acc[i][j][r] = 0.f;

    auto issue = [&](int c) {
        if (c < GNCH) {
            const uint32_t sbase = sb + (c % GSTAGES) * GSTAGE_B;
            const size_t koff = (size_t)c * GBK;
#pragma unroll
            for (int i = 0; i < 8; i++) {
                int q = tid + i * 256;
                int t = q >> 10, r = (q >> 3) & 127, ch = q & 7;
                cpasync16(sbase + t * GTILE_B + (r * GPITCH + ch * 8) * 2,
                          gsrc[t] + (size_t)r * DM + koff + ch * 8);
            }
        }
        asm volatile("cp.async.commit_group;");
    };

    issue(0); issue(1);

    const int a_r = (lane & 7) + ((lane >> 3) & 1) * 8;
    const int a_c = (lane >> 4) * 8;
    const int b_r = (lane & 7) + ((lane >> 4) & 1) * 8;
    const int b_c = ((lane >> 3) & 1) * 8;

    for (int c = 0; c < GNCH; c++) {
        asm volatile("cp.async.wait_group %0;" :: "n"(1));
        __syncthreads();
        issue(c + 2);

        const uint32_t st = sb + (c % GSTAGES) * GSTAGE_B;
        const uint32_t sA = st, sB = st + GTILE_B;

#pragma unroll
        for (int k16 = 0; k16 < 4; k16++) {
            const int kc = k16 * 16;
            uint32_t ah[4][4], bh[2][4];
#pragma unroll
            for (int mfi = 0; mfi < 4; mfi++)
                ldsm_x4(ah[mfi], sA + ((wm * 64 + mfi * 16 + a_r) * GPITCH + kc + a_c) * 2);
#pragma unroll
            for (int nfp = 0; nfp < 2; nfp++)
                ldsm_x4(bh[nfp], sB + ((wn * 32 + nfp * 16 + b_r) * GPITCH + kc + b_c) * 2);
#pragma unroll
            for (int mfi = 0; mfi < 4; mfi++)
#pragma unroll
                for (int nf = 0; nf < 4; nf++)
                    mma_f16(acc[mfi][nf], ah[mfi], &bh[nf >> 1][(nf & 1) * 2]);
        }
    }

#pragma unroll
    for (int mfi = 0; mfi < 4; mfi++)
#pragma unroll
        for (int nf = 0; nf < 4; nf++) {
            int row = bm * BM + wm * 64 + mfi * 16 + (lane >> 2);
            int col = bn * BN + wn * 32 + nf * 8 + (lane & 3) * 2;
            float v0 = acc[mfi][nf][0] * scale, v1 = acc[mfi][nf][1] * scale;
            float v2 = acc[mfi][nf][2] * scale, v3 = acc[mfi][nf][3] * scale;
            if (OMODE == 0) {
                *(float2*)&C[(size_t)row * DM + col]       = make_float2(v0, v1);
                *(float2*)&C[(size_t)(row + 8) * DM + col] = make_float2(v2, v3);
            } else {
                *(uint32_t*)&Ch[(size_t)row * DM + col]       = cvt_f16x2(v0, v1);
                *(uint32_t*)&Ch[(size_t)(row + 8) * DM + col] = cvt_f16x2(v2, v3);
            }
        }
}

__global__ __launch_bounds__(256, 2)
void qkv_mma_kernel()
{
    const int z = blockIdx.z;
    if (z == 0)
        gemm_body<2>(g_x, g_wf[0], nullptr, g_q, ATT_SCALE * LOG2E);
    else if (z == 1)
        gemm_body<2>(g_x, g_wf[1], nullptr, g_k, 1.f);
    else
        gemm_body<2>(g_x, g_wf[2], nullptr, g_v, 1.f);
}
__global__ __launch_bounds__(256, 2)
void out_mma_kernel(float* __restrict__ out)
{
    gemm_body<0>(g_a, g_wf[3], out, nullptr, 1.f);
}

// ---- conversions --------------------------------------------------------------
__global__ __launch_bounds__(256) void conv_x_kernel(const float* __restrict__ s) {
    int i = blockIdx.x * 256 + threadIdx.x;
    float4 v = ((const float4*)s)[i];
    ((uint32_t*)g_x)[i*2+0] = cvt_f16x2(v.x, v.y);
    ((uint32_t*)g_x)[i*2+1] = cvt_f16x2(v.z, v.w);
}
__global__ __launch_bounds__(256) void conv_wt_kernel(const float* __restrict__ W0,
                                                      const float* __restrict__ W1,
                                                      const float* __restrict__ W2,
                                                      const float* __restrict__ W3) {
    __shared__ float tile[32][33];
    const int z = blockIdx.z;
    const float* W = (z == 0) ? W0 : (z == 1) ? W1 : (z == 2) ? W2 : W3;
    const int n0 = blockIdx.x * 32, k0 = blockIdx.y * 32;
    const int tx = threadIdx.x, ty = threadIdx.y;
#pragma unroll
    for (int i = ty; i < 32; i += 8)
        tile[i][tx] = W[(size_t)(k0 + i) * DM + n0 + tx];
    __syncthreads();
#pragma unroll
    for (int i = ty; i < 32; i += 8)
        g_wf[z][(size_t)(n0 + i) * DM + k0 + tx] = __float2half_rn(tile[tx][i]);
}

// ---- Flash attention: pad-flag skip, deferred l, 4-stage K/V ring -----------------
__global__ __launch_bounds__(256, 2)
void attn_kernel(const unsigned char* __restrict__ pad)
{
    extern __shared__ char smem[];
    const uint32_t sb = smem_to_u32(smem);
    const int tid = threadIdx.x, lane = tid & 31, wq = tid >> 5;
    const int b = blockIdx.y >> 4, h = blockIdx.y & 15;
    const int bx = (gridDim.x - 1) - blockIdx.x;   // heavy blocks first
    const int qbase = bx * 128;
    const int ntiles = bx * 2 + 2;

    // Q load (bundled into commit group 0)
    {
        const __half* srcq = g_q + (size_t)(b * SEQ + qbase) * DM + h * HD;
#pragma unroll
        for (int i = 0; i < 4; i++) {
            int q = tid + i * 256;
            int row = q >> 3, ch = q & 7;
            cpasync16(sb + AOFF_Q + (row * APITCH + ch * 8) * 2,
                      srcq + (size_t)row * DM + ch * 8);
        }
    }

    auto issue = [&](int t) {
        if (t < ntiles) {
            const int k0 = t * 64;
            const uint32_t sbase = sb + AOFF_ST + (t % ASTAGES) * ASTG_B;
            const __half* gs[2] = {
                g_k + (size_t)(b * SEQ + k0) * DM + h * HD,
                g_v + (size_t)(b * SEQ + k0) * DM + h * HD };
#pragma unroll
            for (int i = 0; i < 4; i++) {
                int q = tid + i * 256;
                int tt = q >> 9, row = (q >> 3) & 63, ch = q & 7;
                cpasync16(sbase + tt * AK_B + (row * APITCH + ch * 8) * 2,
                          gs[tt] + (size_t)row * DM + ch * 8);
            }
        }
        asm volatile("cp.async.commit_group;");
    };
    // pm values + per-warp-half pad ballot flag
    auto pmload = [&](int t) {
        if (t < ntiles && tid < 64) {
            unsigned char p = pad[b * SEQ + t * 64 + tid];
            float v = p ? -CUDART_INF_F : 0.f;
            const int stg = t % ASTAGES;
            *(float*)(smem + AOFF_PM + stg * APM_STRIDE + tid * 4) = v;
            unsigned bal = __ballot_sync(0xffffffff, p != 0);
            if ((tid & 31) == 0)
                *(uint32_t*)(smem + AOFF_PM + stg * APM_STRIDE + 256 + (tid >> 5) * 4) = bal;
        }
    };

    pmload(0); issue(0);
    pmload(1); issue(1);
    pmload(2); issue(2);

    const int r  = lane >> 2;
    const int c2 = (lane & 3) * 2;
    const int row0 = qbase + wq * 16 + r;
    const int row1 = row0 + 8;
    const int qmax = qbase + wq * 16 + 15;

    const int a_r = (lane & 7) + ((lane >> 3) & 1) * 8;
    const int a_c = (lane >> 4) * 8;
    const int b_r = (lane & 7) + ((lane >> 4) & 1) * 8;
    const int b_c = ((lane >> 3) & 1) * 8;
    const int v_r = (lane & 7) + ((lane >> 3) & 1) * 8;
    const int v_c = (lane >> 4) * 8;

    float m0 = -CUDART_INF_F, m1 = -CUDART_INF_F;
    float l0 = 0.f, l1 = 0.f;            // per-lane partials (reduced in epilogue)
    float o[8][4];
#pragma unroll
    for (int i = 0; i < 8; i++)
#pragma unroll
        for (int j = 0; j < 4; j++) o[i][j] = 0.f;

    uint32_t qf[4][4];

    for (int t = 0; t < ntiles; t++) {
        asm volatile("cp.async.wait_group %0;" :: "n"(2));
        __syncthreads();

        if (t == 0) {
#pragma unroll
            for (int dk = 0; dk < 4; dk++)
                ldsm_x4(qf[dk], sb + AOFF_Q + ((wq * 16 + a_r) * APITCH + dk * 16 + a_c) * 2);
        }
        pmload(t + 3);
        issue(t + 3);   // refills ring slot (t-1)%4, consumed before this barrier

        const int k0 = t * 64;
        if (k0 <= qmax) {
            const uint32_t st = sb + AOFF_ST + (t % ASTAGES) * ASTG_B;
            const uint32_t pmb = (uint32_t)(uintptr_t)(smem + AOFF_PM + (t % ASTAGES) * APM_STRIDE);

            // ---- S = Q K^T, single-pass fp16 ----
            float s[8][4];
#pragma unroll
            for (int f = 0; f < 8; f++)
#pragma unroll
                for (int j = 0; j < 4; j++) s[f][j] = 0.f;

#pragma unroll
            for (int dk = 0; dk < 4; dk++) {
                uint32_t kf[4][4];
#pragma unroll
                for (int g = 0; g < 4; g++)
                    ldsm_x4(kf[g], st + ((g * 16 + b_r) * APITCH + dk * 16 + b_c) * 2);
#pragma unroll
                for (int f = 0; f < 8; f++)
                    mma_f16(s[f], qf[dk], &kf[f >> 1][(f & 1) * 2]);
            }

            // ---- pad mask (only when this 64-key chunk has pad tokens) ----
            {
                const uint2 flg = *(const uint2*)(smem + AOFF_PM + (t % ASTAGES) * APM_STRIDE + 256);
                if (flg.x | flg.y) {
#pragma unroll
                    for (int f = 0; f < 8; f++) {
                        float2 pmv = *(float2*)(smem + AOFF_PM + (t % ASTAGES) * APM_STRIDE + (f * 8 + c2) * 4);
                        s[f][0] += pmv.x; s[f][1] += pmv.y;
                        s[f][2] += pmv.x; s[f][3] += pmv.y;
                    }
                }
            }
            // ---- causal mask (diagonal tiles only) ----
            if (k0 + 63 > row0) {
#pragma unroll
                for (int f = 0; f < 8; f++) {
                    int k = k0 + f * 8 + c2;
                    if (k     > row0) s[f][0] = -CUDART_INF_F;
                    if (k + 1 > row0) s[f][1] = -CUDART_INF_F;
                    if (k     > row1) s[f][2] = -CUDART_INF_F;
                    if (k + 1 > row1) s[f][3] = -CUDART_INF_F;
                }
            }

            // ---- online softmax (base 2), deferred l ----
            float mx0 = -CUDART_INF_F, mx1 = -CUDART_INF_F;
#pragma unroll
            for (int f = 0; f < 8; f++) {
                mx0 = fmaxf(mx0, fmaxf(s[f][0], s[f][1]));
                mx1 = fmaxf(mx1, fmaxf(s[f][2], s[f][3]));
            }
            mx0 = fmaxf(mx0, __shfl_xor_sync(0xffffffff, mx0, 1));
            mx0 = fmaxf(mx0, __shfl_xor_sync(0xffffffff, mx0, 2));
            mx1 = fmaxf(mx1, __shfl_xor_sync(0xffffffff, mx1, 1));
            mx1 = fmaxf(mx1, __shfl_xor_sync(0xffffffff, mx1, 2));
            const float mn0 = fmaxf(m0, mx0), mn1 = fmaxf(m1, mx1);
            const float al0 = exp2f(m0 - mn0), al1 = exp2f(m1 - mn1);
            m0 = mn0; m1 = mn1;

            uint32_t pah[4][4];
            float rs0 = 0.f, rs1 = 0.f;
#pragma unroll
            for (int f = 0; f < 8; f++) {
                float p0 = exp2f(s[f][0] - mn0), p1 = exp2f(s[f][1] - mn0);
                float p2 = exp2f(s[f][2] - mn1), p3 = exp2f(s[f][3] - mn1);
                rs0 += p0 + p1; rs1 += p2 + p3;
                const int ks = f >> 1, hi = (f & 1) * 2;
                pah[ks][hi]     = cvt_f16x2(p0, p1);
                pah[ks][hi + 1] = cvt_f16x2(p2, p3);
            }
            l0 = l0 * al0 + rs0;          // per-lane partial; no shuffles here
            l1 = l1 * al1 + rs1;

#pragma unroll
            for (int nd = 0; nd < 8; nd++) {
                o[nd][0] *= al0; o[nd][1] *= al0;
                o[nd][2] *= al1; o[nd][3] *= al1;
            }

            // ---- O += P V, single-pass fp16 ----
#pragma unroll
            for (int ks = 0; ks < 4; ks++) {
                uint32_t vf[4][4];
#pragma unroll
                for (int g = 0; g < 4; g++)
                    ldsm_x4_t(vf[g], st + AK_B + ((ks * 16 + v_r) * APITCH + g * 16 + v_c) * 2);
#pragma unroll
                for (int nd = 0; nd < 8; nd++)
                    mma_f16(o[nd], pah[ks], &vf[nd >> 1][(nd & 1) * 2]);
            }
        }
    }

    // ---- epilogue: reduce l across the quad, then O/l -> fp16 into g_a ----
    l0 += __shfl_xor_sync(0xffffffff, l0, 1);
    l0 += __shfl_xor_sync(0xffffffff, l0, 2);
    l1 += __shfl_xor_sync(0xffffffff, l1, 1);
    l1 += __shfl_xor_sync(0xffffffff, l1, 2);
    const float inv0 = (l0 > 0.f) ? (1.f / l0) : 0.f;
    const float inv1 = (l1 > 0.f) ? (1.f / l1) : 0.f;
    const size_t r0off = (size_t)(b * SEQ + row0) * DM + h * HD;
    const size_t r1off = (size_t)(b * SEQ + row1) * DM + h * HD;
#pragma unroll
    for (int nd = 0; nd < 8; nd++) {
        const int col = nd * 8 + c2;
        *(uint32_t*)&g_a[r0off + col] = cvt_f16x2(o[nd][0] * inv0, o[nd][1] * inv0);
        *(uint32_t*)&g_a[r1off + col] = cvt_f16x2(o[nd][2] * inv1, o[nd][3] * inv1);
    }
}

// ---- Launch ------------------------------------------------------------------------
extern "C" void kernel_launch(void* const* d_in, const int* in_sizes, int n_in,
                              void* d_out, int out_size)
{
    (void)in_sizes; (void)n_in; (void)out_size;
    const float*         x   = (const float*)d_in[0];
    const unsigned char* pad = (const unsigned char*)d_in[1];
    const float*         Wq  = (const float*)d_in[2];
    const float*         Wk  = (const float*)d_in[3];
    const float*         Wv  = (const float*)d_in[4];
    const float*         Wo  = (const float*)d_in[5];
    float*               out = (float*)d_out;

    cudaFuncSetAttribute(qkv_mma_kernel, cudaFuncAttributeMaxDynamicSharedMemorySize, GEMM_SMEM);
    cudaFuncSetAttribute(out_mma_kernel, cudaFuncAttributeMaxDynamicSharedMemorySize, GEMM_SMEM);
    cudaFuncSetAttribute(attn_kernel, cudaFuncAttributeMaxDynamicSharedMemorySize, ATTN_SMEM);

    conv_x_kernel<<<MROWS * DM / 4 / 256, 256>>>(x);
    conv_wt_kernel<<<dim3(DM / 32, DM / 32, 4), dim3(32, 8)>>>(Wq, Wk, Wv, Wo);

    qkv_mma_kernel<<<dim3(DM / BN, MROWS / BM, 3), 256, GEMM_SMEM>>>();

    attn_kernel<<<dim3(SEQ / 128, BATCH * NH), 256, ATTN_SMEM>>>(pad);

    out_mma_kernel<<<dim3(DM / BN, MROWS / BM), 256, GEMM_SMEM>>>(out);
}

// round 15
// speedup vs baseline: 1.1473x; 1.0282x over previous
#include <cuda_runtime.h>
#include <cuda_bf16.h>
#include <cuda_fp16.h>
#include <math_constants.h>
#include <cstdint>

// ---------------------------------------------------------------------------
// MHA Round 15: attention MUFU relief.
//  - p via ex2.approx.f16x2 (MUFU per warp-tile 34 -> 10)
//  - l via ones-fragment mma (row sums of fp16 P, consistent num/denom)
// GEMMs unchanged from R14 (BK=64, 3-stage, 2 CTAs/SM).
// ---------------------------------------------------------------------------

#define BATCH 4
#define SEQ   2048
#define DM    1024
#define NH    16
#define HD    64
#define MROWS (BATCH * SEQ)
#define ATT_SCALE 0.125f
#define LOG2E 1.44269504088896340736f

// GEMM tiling: 128x128 block, BK=64 chunks
#define BM 128
#define BN 128
#define GBK 64
#define GNCH (DM / GBK)                     // 16
#define GSTAGES 3
#define GPITCH 72
#define GTILE_B (128 * GPITCH * 2)          // 18432
#define GSTAGE_B (2 * GTILE_B)              // 36864
#define GEMM_SMEM (GSTAGES * GSTAGE_B)      // 110592

// attention smem
#define APITCH 72
#define AQ_B   (128 * APITCH * 2)           // 18432 (single Q)
#define AK_B   (64 * APITCH * 2)            // 9216 per K/V tile
#define ASTG_B (2 * AK_B)                   // 18432 per stage (K, V)
#define ASTAGES 4
#define APM_STRIDE 320
#define AOFF_Q  0
#define AOFF_ST AQ_B                          // 18432
#define AOFF_PM (AOFF_ST + ASTAGES * ASTG_B)  // 92160
#define ATTN_SMEM (AOFF_PM + ASTAGES * APM_STRIDE)  // 93440

// ---- scratch ----------------------------------------------------------------
__device__ __align__(256) __half g_x [MROWS * DM];
__device__ __align__(256) __half g_q [MROWS * DM];
__device__ __align__(256) __half g_k [MROWS * DM];
__device__ __align__(256) __half g_v [MROWS * DM];
__device__ __align__(256) __half g_a [MROWS * DM];
__device__ __align__(256) __half g_wf[4][DM * DM];        // W^T fp16: q,k,v,o

// ---- helpers ------------------------------------------------------------------
__device__ __forceinline__ uint32_t smem_to_u32(const void* p) {
    uint32_t a;
    asm("{ .reg .u64 t; cvta.to.shared.u64 t, %1; cvt.u32.u64 %0, t; }"
        : "=r"(a) : "l"(p));
    return a;
}
__device__ __forceinline__ void mma_f16(float* d, const uint32_t* a, const uint32_t* b) {
    asm volatile(
        "mma.sync.aligned.m16n8k16.row.col.f32.f16.f16.f32 "
        "{%0,%1,%2,%3}, {%4,%5,%6,%7}, {%8,%9}, {%0,%1,%2,%3};\n"
        : "+f"(d[0]), "+f"(d[1]), "+f"(d[2]), "+f"(d[3])
        : "r"(a[0]), "r"(a[1]), "r"(a[2]), "r"(a[3]), "r"(b[0]), "r"(b[1]));
}
__device__ __forceinline__ void ldsm_x4(uint32_t* r, uint32_t addr) {
    asm volatile("ldmatrix.sync.aligned.m8n8.x4.shared.b16 {%0,%1,%2,%3}, [%4];"
        : "=r"(r[0]), "=r"(r[1]), "=r"(r[2]), "=r"(r[3]) : "r"(addr));
}
__device__ __forceinline__ void ldsm_x4_t(uint32_t* r, uint32_t addr) {
    asm volatile("ldmatrix.sync.aligned.m8n8.x4.trans.shared.b16 {%0,%1,%2,%3}, [%4];"
        : "=r"(r[0]), "=r"(r[1]), "=r"(r[2]), "=r"(r[3]) : "r"(addr));
}
__device__ __forceinline__ void cpasync16(uint32_t dst, const void* src) {
    asm volatile("cp.async.cg.shared.global [%0], [%1], 16;" :: "r"(dst), "l"(src));
}
__device__ __forceinline__ uint32_t cvt_f16x2(float f_lo, float f_hi) {
    uint32_t r;
    asm("cvt.rn.f16x2.f32 %0, %1, %2;" : "=r"(r) : "f"(f_hi), "f"(f_lo));
    return r;
}
__device__ __forceinline__ uint32_t ex2_f16x2(uint32_t a) {
    uint32_t r;
    asm("ex2.approx.f16x2 %0, %1;" : "=r"(r) : "r"(a));
    return r;
}

// ---- GEMM body: single-pass fp16, BK=64, 3-stage ring (unchanged) ---------------
template<int OMODE>
__device__ __forceinline__ void gemm_body(
    const __half* A_, const __half* B_,
    float* __restrict__ C, __half* __restrict__ Ch, float scale)
{
    extern __shared__ char smem[];
    const uint32_t sb = smem_to_u32(smem);
    const int tid  = threadIdx.x;
    const int lane = tid & 31;
    const int wid  = tid >> 5;
    const int wm   = wid >> 2;
    const int wn   = wid & 3;
    const int bm = blockIdx.y, bn = blockIdx.x;

    const __half* gsrc[2] = {
        A_ + (size_t)bm * BM * DM,
        B_ + (size_t)bn * BN * DM
    };

    float acc[4][4][4];
#pragma unroll
    for (int i = 0; i < 4; i++)
#pragma unroll
        for (int j = 0; j < 4; j++)
#pragma unroll
            for (int r = 0; r < 4; r++) acc[i][j][r] = 0.f;

    auto issue = [&](int c) {
        if (c < GNCH) {
            const uint32_t sbase = sb + (c % GSTAGES) * GSTAGE_B;
            const size_t koff = (size_t)c * GBK;
#pragma unroll
            for (int i = 0; i < 8; i++) {
                int q = tid + i * 256;
                int t = q >> 10, r = (q >> 3) & 127, ch = q & 7;
                cpasync16(sbase + t * GTILE_B + (r * GPITCH + ch * 8) * 2,
                          gsrc[t] + (size_t)r * DM + koff + ch * 8);
            }
        }
        asm volatile("cp.async.commit_group;");
    };

    issue(0); issue(1);

    const int a_r = (lane & 7) + ((lane >> 3) & 1) * 8;
    const int a_c = (lane >> 4) * 8;
    const int b_r = (lane & 7) + ((lane >> 4) & 1) * 8;
    const int b_c = ((lane >> 3) & 1) * 8;

    for (int c = 0; c < GNCH; c++) {
        asm volatile("cp.async.wait_group %0;" :: "n"(1));
        __syncthreads();
        issue(c + 2);

        const uint32_t st = sb + (c % GSTAGES) * GSTAGE_B;
        const uint32_t sA = st, sB = st + GTILE_B;

#pragma unroll
        for (int k16 = 0; k16 < 4; k16++) {
            const int kc = k16 * 16;
            uint32_t ah[4][4], bh[2][4];
#pragma unroll
            for (int mfi = 0; mfi < 4; mfi++)
                ldsm_x4(ah[mfi], sA + ((wm * 64 + mfi * 16 + a_r) * GPITCH + kc + a_c) * 2);
#pragma unroll
            for (int nfp = 0; nfp < 2; nfp++)
                ldsm_x4(bh[nfp], sB + ((wn * 32 + nfp * 16 + b_r) * GPITCH + kc + b_c) * 2);
#pragma unroll
            for (int mfi = 0; mfi < 4; mfi++)
#pragma unroll
                for (int nf = 0; nf < 4; nf++)
                    mma_f16(acc[mfi][nf], ah[mfi], &bh[nf >> 1][(nf & 1) * 2]);
        }
    }

#pragma unroll
    for (int mfi = 0; mfi < 4; mfi++)
#pragma unroll
        for (int nf = 0; nf < 4; nf++) {
            int row = bm * BM + wm * 64 + mfi * 16 + (lane >> 2);
            int col = bn * BN + wn * 32 + nf * 8 + (lane & 3) * 2;
            float v0 = acc[mfi][nf][0] * scale, v1 = acc[mfi][nf][1] * scale;
            float v2 = acc[mfi][nf][2] * scale, v3 = acc[mfi][nf][3] * scale;
            if (OMODE == 0) {
                *(float2*)&C[(size_t)row * DM + col]       = make_float2(v0, v1);
                *(float2*)&C[(size_t)(row + 8) * DM + col] = make_float2(v2, v3);
            } else {
                *(uint32_t*)&Ch[(size_t)row * DM + col]       = cvt_f16x2(v0, v1);
                *(uint32_t*)&Ch[(size_t)(row + 8) * DM + col] = cvt_f16x2(v2, v3);
            }
        }
}

__global__ __launch_bounds__(256, 2)
void qkv_mma_kernel()
{
    const int z = blockIdx.z;
    if (z == 0)
        gemm_body<2>(g_x, g_wf[0], nullptr, g_q, ATT_SCALE * LOG2E);
    else if (z == 1)
        gemm_body<2>(g_x, g_wf[1], nullptr, g_k, 1.f);
    else
        gemm_body<2>(g_x, g_wf[2], nullptr, g_v, 1.f);
}
__global__ __launch_bounds__(256, 2)
void out_mma_kernel(float* __restrict__ out)
{
    gemm_body<0>(g_a, g_wf[3], out, nullptr, 1.f);
}

// ---- conversions --------------------------------------------------------------
__global__ __launch_bounds__(256) void conv_x_kernel(const float* __restrict__ s) {
    int i = blockIdx.x * 256 + threadIdx.x;
    float4 v = ((const float4*)s)[i];
    ((uint32_t*)g_x)[i*2+0] = cvt_f16x2(v.x, v.y);
    ((uint32_t*)g_x)[i*2+1] = cvt_f16x2(v.z, v.w);
}
__global__ __launch_bounds__(256) void conv_wt_kernel(const float* __restrict__ W0,
                                                      const float* __restrict__ W1,
                                                      const float* __restrict__ W2,
                                                      const float* __restrict__ W3) {
    __shared__ float tile[32][33];
    const int z = blockIdx.z;
    const float* W = (z == 0) ? W0 : (z == 1) ? W1 : (z == 2) ? W2 : W3;
    const int n0 = blockIdx.x * 32, k0 = blockIdx.y * 32;
    const int tx = threadIdx.x, ty = threadIdx.y;
#pragma unroll
    for (int i = ty; i < 32; i += 8)
        tile[i][tx] = W[(size_t)(k0 + i) * DM + n0 + tx];
    __syncthreads();
#pragma unroll
    for (int i = ty; i < 32; i += 8)
        g_wf[z][(size_t)(n0 + i) * DM + k0 + tx] = __float2half_rn(tile[tx][i]);
}

// ---- Flash attention: f16x2 ex2 + ones-mma l ---------------------------------------
__global__ __launch_bounds__(256, 2)
void attn_kernel(const unsigned char* __restrict__ pad)
{
    extern __shared__ char smem[];
    const uint32_t sb = smem_to_u32(smem);
    const int tid = threadIdx.x, lane = tid & 31, wq = tid >> 5;
    const int b = blockIdx.y >> 4, h = blockIdx.y & 15;
    const int bx = (gridDim.x - 1) - blockIdx.x;   // heavy blocks first
    const int qbase = bx * 128;
    const int ntiles = bx * 2 + 2;

    // Q load (bundled into commit group 0)
    {
        const __half* srcq = g_q + (size_t)(b * SEQ + qbase) * DM + h * HD;
#pragma unroll
        for (int i = 0; i < 4; i++) {
            int q = tid + i * 256;
            int row = q >> 3, ch = q & 7;
            cpasync16(sb + AOFF_Q + (row * APITCH + ch * 8) * 2,
                      srcq + (size_t)row * DM + ch * 8);
        }
    }

    auto issue = [&](int t) {
        if (t < ntiles) {
            const int k0 = t * 64;
            const uint32_t sbase = sb + AOFF_ST + (t % ASTAGES) * ASTG_B;
            const __half* gs[2] = {
                g_k + (size_t)(b * SEQ + k0) * DM + h * HD,
                g_v + (size_t)(b * SEQ + k0) * DM + h * HD };
#pragma unroll
            for (int i = 0; i < 4; i++) {
                int q = tid + i * 256;
                int tt = q >> 9, row = (q >> 3) & 63, ch = q & 7;
                cpasync16(sbase + tt * AK_B + (row * APITCH + ch * 8) * 2,
                          gs[tt] + (size_t)row * DM + ch * 8);
            }
        }
        asm volatile("cp.async.commit_group;");
    };
    auto pmload = [&](int t) {
        if (t < ntiles && tid < 64) {
            unsigned char p = pad[b * SEQ + t * 64 + tid];
            float v = p ? -CUDART_INF_F : 0.f;
            const int stg = t % ASTAGES;
            *(float*)(smem + AOFF_PM + stg * APM_STRIDE + tid * 4) = v;
            unsigned bal = __ballot_sync(0xffffffff, p != 0);
            if ((tid & 31) == 0)
                *(uint32_t*)(smem + AOFF_PM + stg * APM_STRIDE + 256 + (tid >> 5) * 4) = bal;
        }
    };

    pmload(0); issue(0);
    pmload(1); issue(1);
    pmload(2); issue(2);

    const int r  = lane >> 2;
    const int c2 = (lane & 3) * 2;
    const int row0 = qbase + wq * 16 + r;
    const int row1 = row0 + 8;
    const int qmax = qbase + wq * 16 + 15;

    const int a_r = (lane & 7) + ((lane >> 3) & 1) * 8;
    const int a_c = (lane >> 4) * 8;
    const int b_r = (lane & 7) + ((lane >> 4) & 1) * 8;
    const int b_c = ((lane >> 3) & 1) * 8;
    const int v_r = (lane & 7) + ((lane >> 3) & 1) * 8;
    const int v_c = (lane >> 4) * 8;

    const uint32_t ONE2 = 0x3C003C00u;              // fp16 {1.0, 1.0}
    const uint32_t onesb[2] = {ONE2, ONE2};

    float m0 = -CUDART_INF_F, m1 = -CUDART_INF_F;
    float o_l[4] = {0.f, 0.f, 0.f, 0.f};            // row-sum accumulator (l)
    float o[8][4];
#pragma unroll
    for (int i = 0; i < 8; i++)
#pragma unroll
        for (int j = 0; j < 4; j++) o[i][j] = 0.f;

    uint32_t qf[4][4];

    for (int t = 0; t < ntiles; t++) {
        asm volatile("cp.async.wait_group %0;" :: "n"(2));
        __syncthreads();

        if (t == 0) {
#pragma unroll
            for (int dk = 0; dk < 4; dk++)
                ldsm_x4(qf[dk], sb + AOFF_Q + ((wq * 16 + a_r) * APITCH + dk * 16 + a_c) * 2);
        }
        pmload(t + 3);
        issue(t + 3);

        const int k0 = t * 64;
        if (k0 <= qmax) {
            const uint32_t st = sb + AOFF_ST + (t % ASTAGES) * ASTG_B;

            // ---- S = Q K^T, single-pass fp16 ----
            float s[8][4];
#pragma unroll
            for (int f = 0; f < 8; f++)
#pragma unroll
                for (int j = 0; j < 4; j++) s[f][j] = 0.f;

#pragma unroll
            for (int dk = 0; dk < 4; dk++) {
                uint32_t kf[4][4];
#pragma unroll
                for (int g = 0; g < 4; g++)
                    ldsm_x4(kf[g], st + ((g * 16 + b_r) * APITCH + dk * 16 + b_c) * 2);
#pragma unroll
                for (int f = 0; f < 8; f++)
                    mma_f16(s[f], qf[dk], &kf[f >> 1][(f & 1) * 2]);
            }

            // ---- pad mask (only when this 64-key chunk has pad tokens) ----
            {
                const uint2 flg = *(const uint2*)(smem + AOFF_PM + (t % ASTAGES) * APM_STRIDE + 256);
                if (flg.x | flg.y) {
#pragma unroll
                    for (int f = 0; f < 8; f++) {
                        float2 pmv = *(float2*)(smem + AOFF_PM + (t % ASTAGES) * APM_STRIDE + (f * 8 + c2) * 4);
                        s[f][0] += pmv.x; s[f][1] += pmv.y;
                        s[f][2] += pmv.x; s[f][3] += pmv.y;
                    }
                }
            }
            // ---- causal mask (diagonal tiles only) ----
            if (k0 + 63 > row0) {
#pragma unroll
                for (int f = 0; f < 8; f++) {
                    int k = k0 + f * 8 + c2;
                    if (k     > row0) s[f][0] = -CUDART_INF_F;
                    if (k + 1 > row0) s[f][1] = -CUDART_INF_F;
                    if (k     > row1) s[f][2] = -CUDART_INF_F;
                    if (k + 1 > row1) s[f][3] = -CUDART_INF_F;
                }
            }

            // ---- online softmax (base 2), p via f16x2 ex2 ----
            float mx0 = -CUDART_INF_F, mx1 = -CUDART_INF_F;
#pragma unroll
            for (int f = 0; f < 8; f++) {
                mx0 = fmaxf(mx0, fmaxf(s[f][0], s[f][1]));
                mx1 = fmaxf(mx1, fmaxf(s[f][2], s[f][3]));
            }
            mx0 = fmaxf(mx0, __shfl_xor_sync(0xffffffff, mx0, 1));
            mx0 = fmaxf(mx0, __shfl_xor_sync(0xffffffff, mx0, 2));
            mx1 = fmaxf(mx1, __shfl_xor_sync(0xffffffff, mx1, 1));
            mx1 = fmaxf(mx1, __shfl_xor_sync(0xffffffff, mx1, 2));
            const float mn0 = fmaxf(m0, mx0), mn1 = fmaxf(m1, mx1);
            const float al0 = exp2f(m0 - mn0), al1 = exp2f(m1 - mn1);
            m0 = mn0; m1 = mn1;

            uint32_t pah[4][4];
#pragma unroll
            for (int f = 0; f < 8; f++) {
                const int ks = f >> 1, hi = (f & 1) * 2;
                pah[ks][hi]     = ex2_f16x2(cvt_f16x2(s[f][0] - mn0, s[f][1] - mn0));
                pah[ks][hi + 1] = ex2_f16x2(cvt_f16x2(s[f][2] - mn1, s[f][3] - mn1));
            }

            // rescale accumulators (incl. l accumulator)
            o_l[0] *= al0; o_l[2] *= al1;
#pragma unroll
            for (int nd = 0; nd < 8; nd++) {
                o[nd][0] *= al0; o[nd][1] *= al0;
                o[nd][2] *= al1; o[nd][3] *= al1;
            }

            // ---- O += P V (+ ones-mma for l), single-pass fp16 ----
#pragma unroll
            for (int ks = 0; ks < 4; ks++) {
                uint32_t vf[4][4];
#pragma unroll
                for (int g = 0; g < 4; g++)
                    ldsm_x4_t(vf[g], st + AK_B + ((ks * 16 + v_r) * APITCH + g * 16 + v_c) * 2);
#pragma unroll
                for (int nd = 0; nd < 8; nd++)
                    mma_f16(o[nd], pah[ks], &vf[nd >> 1][(nd & 1) * 2]);
                mma_f16(o_l, pah[ks], onesb);   // row sums -> l
            }
        }
    }

    // ---- epilogue: l from ones-mma accumulator (every lane has its row's sum) ----
    const float l0 = o_l[0], l1 = o_l[2];
    const float inv0 = (l0 > 0.f) ? (1.f / l0) : 0.f;
    const float inv1 = (l1 > 0.f) ? (1.f / l1) : 0.f;
    const size_t r0off = (size_t)(b * SEQ + row0) * DM + h * HD;
    const size_t r1off = (size_t)(b * SEQ + row1) * DM + h * HD;
#pragma unroll
    for (int nd = 0; nd < 8; nd++) {
        const int col = nd * 8 + c2;
        *(uint32_t*)&g_a[r0off + col] = cvt_f16x2(o[nd][0] * inv0, o[nd][1] * inv0);
        *(uint32_t*)&g_a[r1off + col] = cvt_f16x2(o[nd][2] * inv1, o[nd][3] * inv1);
    }
}

// ---- Launch ------------------------------------------------------------------------
extern "C" void kernel_launch(void* const* d_in, const int* in_sizes, int n_in,
                              void* d_out, int out_size)
{
    (void)in_sizes; (void)n_in; (void)out_size;
    const float*         x   = (const float*)d_in[0];
    const unsigned char* pad = (const unsigned char*)d_in[1];
    const float*         Wq  = (const float*)d_in[2];
    const float*         Wk  = (const float*)d_in[3];
    const float*         Wv  = (const float*)d_in[4];
    const float*         Wo  = (const float*)d_in[5];
    float*               out = (float*)d_out;

    cudaFuncSetAttribute(qkv_mma_kernel, cudaFuncAttributeMaxDynamicSharedMemorySize, GEMM_SMEM);
    cudaFuncSetAttribute(out_mma_kernel, cudaFuncAttributeMaxDynamicSharedMemorySize, GEMM_SMEM);
    cudaFuncSetAttribute(attn_kernel, cudaFuncAttributeMaxDynamicSharedMemorySize, ATTN_SMEM);

    conv_x_kernel<<<MROWS * DM / 4 / 256, 256>>>(x);
    conv_wt_kernel<<<dim3(DM / 32, DM / 32, 4), dim3(32, 8)>>>(Wq, Wk, Wv, Wo);

    qkv_mma_kernel<<<dim3(DM / BN, MROWS / BM, 3), 256, GEMM_SMEM>>>();

    attn_kernel<<<dim3(SEQ / 128, BATCH * NH), 256, ATTN_SMEM>>>(pad);

    out_mma_kernel<<<dim3(DM / BN, MROWS / BM), 256, GEMM_SMEM>>>(out);
}

// round 16
// speedup vs baseline: 1.1670x; 1.0172x over previous
#include <cuda_runtime.h>
#include <cuda_bf16.h>
#include <cuda_fp16.h>
#include <math_constants.h>
#include <cstdint>

// ---------------------------------------------------------------------------
// MHA Round 16: R15 + skip-rescale vote in attention softmax (exact), merged
// conversion kernel. GEMMs unchanged (BK=64, 3-stage, 2 CTAs/SM).
// ---------------------------------------------------------------------------

#define BATCH 4
#define SEQ   2048
#define DM    1024
#define NH    16
#define HD    64
#define MROWS (BATCH * SEQ)
#define ATT_SCALE 0.125f
#define LOG2E 1.44269504088896340736f

// GEMM tiling: 128x128 block, BK=64 chunks
#define BM 128
#define BN 128
#define GBK 64
#define GNCH (DM / GBK)                     // 16
#define GSTAGES 3
#define GPITCH 72
#define GTILE_B (128 * GPITCH * 2)          // 18432
#define GSTAGE_B (2 * GTILE_B)              // 36864
#define GEMM_SMEM (GSTAGES * GSTAGE_B)      // 110592

// attention smem
#define APITCH 72
#define AQ_B   (128 * APITCH * 2)           // 18432 (single Q)
#define AK_B   (64 * APITCH * 2)            // 9216 per K/V tile
#define ASTG_B (2 * AK_B)                   // 18432 per stage (K, V)
#define ASTAGES 4
#define APM_STRIDE 320
#define AOFF_Q  0
#define AOFF_ST AQ_B                          // 18432
#define AOFF_PM (AOFF_ST + ASTAGES * ASTG_B)  // 92160
#define ATTN_SMEM (AOFF_PM + ASTAGES * APM_STRIDE)  // 93440

// ---- scratch ----------------------------------------------------------------
__device__ __align__(256) __half g_x [MROWS * DM];
__device__ __align__(256) __half g_q [MROWS * DM];
__device__ __align__(256) __half g_k [MROWS * DM];
__device__ __align__(256) __half g_v [MROWS * DM];
__device__ __align__(256) __half g_a [MROWS * DM];
__device__ __align__(256) __half g_wf[4][DM * DM];        // W^T fp16: q,k,v,o

// ---- helpers ------------------------------------------------------------------
__device__ __forceinline__ uint32_t smem_to_u32(const void* p) {
    uint32_t a;
    asm("{ .reg .u64 t; cvta.to.shared.u64 t, %1; cvt.u32.u64 %0, t; }"
        : "=r"(a) : "l"(p));
    return a;
}
__device__ __forceinline__ void mma_f16(float* d, const uint32_t* a, const uint32_t* b) {
    asm volatile(
        "mma.sync.aligned.m16n8k16.row.col.f32.f16.f16.f32 "
        "{%0,%1,%2,%3}, {%4,%5,%6,%7}, {%8,%9}, {%0,%1,%2,%3};\n"
        : "+f"(d[0]), "+f"(d[1]), "+f"(d[2]), "+f"(d[3])
        : "r"(a[0]), "r"(a[1]), "r"(a[2]), "r"(a[3]), "r"(b[0]), "r"(b[1]));
}
__device__ __forceinline__ void ldsm_x4(uint32_t* r, uint32_t addr) {
    asm volatile("ldmatrix.sync.aligned.m8n8.x4.shared.b16 {%0,%1,%2,%3}, [%4];"
        : "=r"(r[0]), "=r"(r[1]), "=r"(r[2]), "=r"(r[3]) : "r"(addr));
}
__device__ __forceinline__ void ldsm_x4_t(uint32_t* r, uint32_t addr) {
    asm volatile("ldmatrix.sync.aligned.m8n8.x4.trans.shared.b16 {%0,%1,%2,%3}, [%4];"
        : "=r"(r[0]), "=r"(r[1]), "=r"(r[2]), "=r"(r[3]) : "r"(addr));
}
__device__ __forceinline__ void cpasync16(uint32_t dst, const void* src) {
    asm volatile("cp.async.cg.shared.global [%0], [%1], 16;" :: "r"(dst), "l"(src));
}
__device__ __forceinline__ uint32_t cvt_f16x2(float f_lo, float f_hi) {
    uint32_t r;
    asm("cvt.rn.f16x2.f32 %0, %1, %2;" : "=r"(r) : "f"(f_hi), "f"(f_lo));
    return r;
}
__device__ __forceinline__ uint32_t ex2_f16x2(uint32_t a) {
    uint32_t r;
    asm("ex2.approx.f16x2 %0, %1;" : "=r"(r) : "r"(a));
    return r;
}

// ---- GEMM body: single-pass fp16, BK=64, 3-stage ring (unchanged) ---------------
template<int OMODE>
__device__ __forceinline__ void gemm_body(
    const __half* A_, const __half* B_,
    float* __restrict__ C, __half* __restrict__ Ch, float scale)
{
    extern __shared__ char smem[];
    const uint32_t sb = smem_to_u32(smem);
    const int tid  = threadIdx.x;
    const int lane = tid & 31;
    const int wid  = tid >> 5;
    const int wm   = wid >> 2;
    const int wn   = wid & 3;
    const int bm = blockIdx.y, bn = blockIdx.x;

    const __half* gsrc[2] = {
        A_ + (size_t)bm * BM * DM,
        B_ + (size_t)bn * BN * DM
    };

    float acc[4][4][4];
#pragma unroll
    for (int i = 0; i < 4; i++)
#pragma unroll
        for (int j = 0; j < 4; j++)
#pragma unroll
            for (int r = 0; r < 4; r++) acc[i][j][r] = 0.f;

    auto issue = [&](int c) {
        if (c < GNCH) {
            const uint32_t sbase = sb + (c % GSTAGES) * GSTAGE_B;
            const size_t koff = (size_t)c * GBK;
#pragma unroll
            for (int i = 0; i < 8; i++) {
                int q = tid + i * 256;
                int t = q >> 10, r = (q >> 3) & 127, ch = q & 7;
                cpasync16(sbase + t * GTILE_B + (r * GPITCH + ch * 8) * 2,
                          gsrc[t] + (size_t)r * DM + koff + ch * 8);
            }
        }
        asm volatile("cp.async.commit_group;");
    };

    issue(0); issue(1);

    const int a_r = (lane & 7) + ((lane >> 3) & 1) * 8;
    const int a_c = (lane >> 4) * 8;
    const int b_r = (lane & 7) + ((lane >> 4) & 1) * 8;
    const int b_c = ((lane >> 3) & 1) * 8;

    for (int c = 0; c < GNCH; c++) {
        asm volatile("cp.async.wait_group %0;" :: "n"(1));
        __syncthreads();
        issue(c + 2);

        const uint32_t st = sb + (c % GSTAGES) * GSTAGE_B;
        const uint32_t sA = st, sB = st + GTILE_B;

#pragma unroll
        for (int k16 = 0; k16 < 4; k16++) {
            const int kc = k16 * 16;
            uint32_t ah[4][4], bh[2][4];
#pragma unroll
            for (int mfi = 0; mfi < 4; mfi++)
                ldsm_x4(ah[mfi], sA + ((wm * 64 + mfi * 16 + a_r) * GPITCH + kc + a_c) * 2);
#pragma unroll
            for (int nfp = 0; nfp < 2; nfp++)
                ldsm_x4(bh[nfp], sB + ((wn * 32 + nfp * 16 + b_r) * GPITCH + kc + b_c) * 2);
#pragma unroll
            for (int mfi = 0; mfi < 4; mfi++)
#pragma unroll
                for (int nf = 0; nf < 4; nf++)
                    mma_f16(acc[mfi][nf], ah[mfi], &bh[nf >> 1][(nf & 1) * 2]);
        }
    }

#pragma unroll
    for (int mfi = 0; mfi < 4; mfi++)
#pragma unroll
        for (int nf = 0; nf < 4; nf++) {
            int row = bm * BM + wm * 64 + mfi * 16 + (lane >> 2);
            int col = bn * BN + wn * 32 + nf * 8 + (lane & 3) * 2;
            float v0 = acc[mfi][nf][0] * scale, v1 = acc[mfi][nf][1] * scale;
            float v2 = acc[mfi][nf][2] * scale, v3 = acc[mfi][nf][3] * scale;
            if (OMODE == 0) {
                *(float2*)&C[(size_t)row * DM + col]       = make_float2(v0, v1);
                *(float2*)&C[(size_t)(row + 8) * DM + col] = make_float2(v2, v3);
            } else {
                *(uint32_t*)&Ch[(size_t)row * DM + col]       = cvt_f16x2(v0, v1);
                *(uint32_t*)&Ch[(size_t)(row + 8) * DM + col] = cvt_f16x2(v2, v3);
            }
        }
}

__global__ __launch_bounds__(256, 2)
void qkv_mma_kernel()
{
    const int z = blockIdx.z;
    if (z == 0)
        gemm_body<2>(g_x, g_wf[0], nullptr, g_q, ATT_SCALE * LOG2E);
    else if (z == 1)
        gemm_body<2>(g_x, g_wf[1], nullptr, g_k, 1.f);
    else
        gemm_body<2>(g_x, g_wf[2], nullptr, g_v, 1.f);
}
__global__ __launch_bounds__(256, 2)
void out_mma_kernel(float* __restrict__ out)
{
    gemm_body<0>(g_a, g_wf[3], out, nullptr, 1.f);
}

// ---- merged conversion: grid.x < XBLK -> x fp32->fp16; else W transpose ----------
#define XBLK (MROWS * DM / 4 / 256)   // 8192
__global__ __launch_bounds__(256)
void conv_all_kernel(const float* __restrict__ x,
                     const float* __restrict__ W0, const float* __restrict__ W1,
                     const float* __restrict__ W2, const float* __restrict__ W3)
{
    const int bid = blockIdx.x;
    const int tid = threadIdx.x;
    if (bid < XBLK) {
        int i = bid * 256 + tid;
        float4 v = ((const float4*)x)[i];
        ((uint32_t*)g_x)[i*2+0] = cvt_f16x2(v.x, v.y);
        ((uint32_t*)g_x)[i*2+1] = cvt_f16x2(v.z, v.w);
    } else {
        __shared__ float tile[32][33];
        const int wb = bid - XBLK;          // 0..4095
        const int z  = wb >> 10;            // 0..3
        const int t2 = wb & 1023;           // 32x32 tile index
        const float* W = (z == 0) ? W0 : (z == 1) ? W1 : (z == 2) ? W2 : W3;
        const int n0 = (t2 & 31) * 32, k0 = (t2 >> 5) * 32;
        const int tx = tid & 31, ty = tid >> 5;   // 32 x 8
#pragma unroll
        for (int i = ty; i < 32; i += 8)
            tile[i][tx] = W[(size_t)(k0 + i) * DM + n0 + tx];
        __syncthreads();
#pragma unroll
        for (int i = ty; i < 32; i += 8)
            g_wf[z][(size_t)(n0 + i) * DM + k0 + tx] = __float2half_rn(tile[tx][i]);
    }
}

// ---- Flash attention: f16x2 ex2, ones-mma l, skip-rescale vote --------------------
__global__ __launch_bounds__(256, 2)
void attn_kernel(const unsigned char* __restrict__ pad)
{
    extern __shared__ char smem[];
    const uint32_t sb = smem_to_u32(smem);
    const int tid = threadIdx.x, lane = tid & 31, wq = tid >> 5;
    const int b = blockIdx.y >> 4, h = blockIdx.y & 15;
    const int bx = (gridDim.x - 1) - blockIdx.x;   // heavy blocks first
    const int qbase = bx * 128;
    const int ntiles = bx * 2 + 2;

    // Q load (bundled into commit group 0)
    {
        const __half* srcq = g_q + (size_t)(b * SEQ + qbase) * DM + h * HD;
#pragma unroll
        for (int i = 0; i < 4; i++) {
            int q = tid + i * 256;
            int row = q >> 3, ch = q & 7;
            cpasync16(sb + AOFF_Q + (row * APITCH + ch * 8) * 2,
                      srcq + (size_t)row * DM + ch * 8);
        }
    }

    auto issue = [&](int t) {
        if (t < ntiles) {
            const int k0 = t * 64;
            const uint32_t sbase = sb + AOFF_ST + (t % ASTAGES) * ASTG_B;
            const __half* gs[2] = {
                g_k + (size_t)(b * SEQ + k0) * DM + h * HD,
                g_v + (size_t)(b * SEQ + k0) * DM + h * HD };
#pragma unroll
            for (int i = 0; i < 4; i++) {
                int q = tid + i * 256;
                int tt = q >> 9, row = (q >> 3) & 63, ch = q & 7;
                cpasync16(sbase + tt * AK_B + (row * APITCH + ch * 8) * 2,
                          gs[tt] + (size_t)row * DM + ch * 8);
            }
        }
        asm volatile("cp.async.commit_group;");
    };
    auto pmload = [&](int t) {
        if (t < ntiles && tid < 64) {
            unsigned char p = pad[b * SEQ + t * 64 + tid];
            float v = p ? -CUDART_INF_F : 0.f;
            const int stg = t % ASTAGES;
            *(float*)(smem + AOFF_PM + stg * APM_STRIDE + tid * 4) = v;
            unsigned bal = __ballot_sync(0xffffffff, p != 0);
            if ((tid & 31) == 0)
                *(uint32_t*)(smem + AOFF_PM + stg * APM_STRIDE + 256 + (tid >> 5) * 4) = bal;
        }
    };

    pmload(0); issue(0);
    pmload(1); issue(1);
    pmload(2); issue(2);

    const int r  = lane >> 2;
    const int c2 = (lane & 3) * 2;
    const int row0 = qbase + wq * 16 + r;
    const int row1 = row0 + 8;
    const int qmax = qbase + wq * 16 + 15;

    const int a_r = (lane & 7) + ((lane >> 3) & 1) * 8;
    const int a_c = (lane >> 4) * 8;
    const int b_r = (lane & 7) + ((lane >> 4) & 1) * 8;
    const int b_c = ((lane >> 3) & 1) * 8;
    const int v_r = (lane & 7) + ((lane >> 3) & 1) * 8;
    const int v_c = (lane >> 4) * 8;

    const uint32_t ONE2 = 0x3C003C00u;
    const uint32_t onesb[2] = {ONE2, ONE2};

    float m0 = -CUDART_INF_F, m1 = -CUDART_INF_F;
    float o_l[4] = {0.f, 0.f, 0.f, 0.f};
    float o[8][4];
#pragma unroll
    for (int i = 0; i < 8; i++)
#pragma unroll
        for (int j = 0; j < 4; j++) o[i][j] = 0.f;

    uint32_t qf[4][4];

    for (int t = 0; t < ntiles; t++) {
        asm volatile("cp.async.wait_group %0;" :: "n"(2));
        __syncthreads();

        if (t == 0) {
#pragma unroll
            for (int dk = 0; dk < 4; dk++)
                ldsm_x4(qf[dk], sb + AOFF_Q + ((wq * 16 + a_r) * APITCH + dk * 16 + a_c) * 2);
        }
        pmload(t + 3);
        issue(t + 3);

        const int k0 = t * 64;
        if (k0 <= qmax) {
            const uint32_t st = sb + AOFF_ST + (t % ASTAGES) * ASTG_B;

            // ---- S = Q K^T, single-pass fp16 ----
            float s[8][4];
#pragma unroll
            for (int f = 0; f < 8; f++)
#pragma unroll
                for (int j = 0; j < 4; j++) s[f][j] = 0.f;

#pragma unroll
            for (int dk = 0; dk < 4; dk++) {
                uint32_t kf[4][4];
#pragma unroll
                for (int g = 0; g < 4; g++)
                    ldsm_x4(kf[g], st + ((g * 16 + b_r) * APITCH + dk * 16 + b_c) * 2);
#pragma unroll
                for (int f = 0; f < 8; f++)
                    mma_f16(s[f], qf[dk], &kf[f >> 1][(f & 1) * 2]);
            }

            // ---- pad mask (only when this chunk has pad tokens) ----
            {
                const uint2 flg = *(const uint2*)(smem + AOFF_PM + (t % ASTAGES) * APM_STRIDE + 256);
                if (flg.x | flg.y) {
#pragma unroll
                    for (int f = 0; f < 8; f++) {
                        float2 pmv = *(float2*)(smem + AOFF_PM + (t % ASTAGES) * APM_STRIDE + (f * 8 + c2) * 4);
                        s[f][0] += pmv.x; s[f][1] += pmv.y;
                        s[f][2] += pmv.x; s[f][3] += pmv.y;
                    }
                }
            }
            // ---- causal mask (diagonal tiles only) ----
            if (k0 + 63 > row0) {
#pragma unroll
                for (int f = 0; f < 8; f++) {
                    int k = k0 + f * 8 + c2;
                    if (k     > row0) s[f][0] = -CUDART_INF_F;
                    if (k + 1 > row0) s[f][1] = -CUDART_INF_F;
                    if (k     > row1) s[f][2] = -CUDART_INF_F;
                    if (k + 1 > row1) s[f][3] = -CUDART_INF_F;
                }
            }

            // ---- online softmax (base 2), skip-rescale when max unchanged ----
            float mx0 = -CUDART_INF_F, mx1 = -CUDART_INF_F;
#pragma unroll
            for (int f = 0; f < 8; f++) {
                mx0 = fmaxf(mx0, fmaxf(s[f][0], s[f][1]));
                mx1 = fmaxf(mx1, fmaxf(s[f][2], s[f][3]));
            }
            mx0 = fmaxf(mx0, __shfl_xor_sync(0xffffffff, mx0, 1));
            mx0 = fmaxf(mx0, __shfl_xor_sync(0xffffffff, mx0, 2));
            mx1 = fmaxf(mx1, __shfl_xor_sync(0xffffffff, mx1, 1));
            mx1 = fmaxf(mx1, __shfl_xor_sync(0xffffffff, mx1, 2));
            const bool upd = (mx0 > m0) || (mx1 > m1);
            if (__any_sync(0xffffffff, upd)) {
                const float mn0 = fmaxf(m0, mx0), mn1 = fmaxf(m1, mx1);
                const float al0 = exp2f(m0 - mn0), al1 = exp2f(m1 - mn1);
                m0 = mn0; m1 = mn1;
                o_l[0] *= al0; o_l[2] *= al1;
#pragma unroll
                for (int nd = 0; nd < 8; nd++) {
                    o[nd][0] *= al0; o[nd][1] *= al0;
                    o[nd][2] *= al1; o[nd][3] *= al1;
                }
            }

            uint32_t pah[4][4];
#pragma unroll
            for (int f = 0; f < 8; f++) {
                const int ks = f >> 1, hi = (f & 1) * 2;
                pah[ks][hi]     = ex2_f16x2(cvt_f16x2(s[f][0] - m0, s[f][1] - m0));
                pah[ks][hi + 1] = ex2_f16x2(cvt_f16x2(s[f][2] - m1, s[f][3] - m1));
            }

            // ---- O += P V (+ ones-mma for l), single-pass fp16 ----
#pragma unroll
            for (int ks = 0; ks < 4; ks++) {
                uint32_t vf[4][4];
#pragma unroll
                for (int g = 0; g < 4; g++)
                    ldsm_x4_t(vf[g], st + AK_B + ((ks * 16 + v_r) * APITCH + g * 16 + v_c) * 2);
#pragma unroll
                for (int nd = 0; nd < 8; nd++)
                    mma_f16(o[nd], pah[ks], &vf[nd >> 1][(nd & 1) * 2]);
                mma_f16(o_l, pah[ks], onesb);   // row sums -> l
            }
        }
    }

    // ---- epilogue ----
    const float l0 = o_l[0], l1 = o_l[2];
    const float inv0 = (l0 > 0.f) ? (1.f / l0) : 0.f;
    const float inv1 = (l1 > 0.f) ? (1.f / l1) : 0.f;
    const size_t r0off = (size_t)(b * SEQ + row0) * DM + h * HD;
    const size_t r1off = (size_t)(b * SEQ + row1) * DM + h * HD;
#pragma unroll
    for (int nd = 0; nd < 8; nd++) {
        const int col = nd * 8 + c2;
        *(uint32_t*)&g_a[r0off + col] = cvt_f16x2(o[nd][0] * inv0, o[nd][1] * inv0);
        *(uint32_t*)&g_a[r1off + col] = cvt_f16x2(o[nd][2] * inv1, o[nd][3] * inv1);
    }
}

// ---- Launch ------------------------------------------------------------------------
extern "C" void kernel_launch(void* const* d_in, const int* in_sizes, int n_in,
                              void* d_out, int out_size)
{
    (void)in_sizes; (void)n_in; (void)out_size;
    const float*         x   = (const float*)d_in[0];
    const unsigned char* pad = (const unsigned char*)d_in[1];
    const float*         Wq  = (const float*)d_in[2];
    const float*         Wk  = (const float*)d_in[3];
    const float*         Wv  = (const float*)d_in[4];
    const float*         Wo  = (const float*)d_in[5];
    float*               out = (float*)d_out;

    cudaFuncSetAttribute(qkv_mma_kernel, cudaFuncAttributeMaxDynamicSharedMemorySize, GEMM_SMEM);
    cudaFuncSetAttribute(out_mma_kernel, cudaFuncAttributeMaxDynamicSharedMemorySize, GEMM_SMEM);
    cudaFuncSetAttribute(attn_kernel, cudaFuncAttributeMaxDynamicSharedMemorySize, ATTN_SMEM);

    conv_all_kernel<<<XBLK + 4096, 256>>>(x, Wq, Wk, Wv, Wo);

    qkv_mma_kernel<<<dim3(DM / BN, MROWS / BM, 3), 256, GEMM_SMEM>>>();

    attn_kernel<<<dim3(SEQ / 128, BATCH * NH), 256, ATTN_SMEM>>>(pad);

    out_mma_kernel<<<dim3(DM / BN, MROWS / BM), 256, GEMM_SMEM>>>(out);
}

// round 17
// speedup vs baseline: 1.1714x; 1.0038x over previous
#include <cuda_runtime.h>
#include <cuda_bf16.h>
#include <cuda_fp16.h>
#include <math_constants.h>
#include <cstdint>

// ---------------------------------------------------------------------------
// MHA Round 17: R16 + pre-shuffle early-exit vote in attention softmax
// (skips the 4 butterfly shuffles AND rescale when no lane's local max beats
// the running max — bit-exact). GEMMs/conv unchanged.
// ---------------------------------------------------------------------------

#define BATCH 4
#define SEQ   2048
#define DM    1024
#define NH    16
#define HD    64
#define MROWS (BATCH * SEQ)
#define ATT_SCALE 0.125f
#define LOG2E 1.44269504088896340736f

// GEMM tiling: 128x128 block, BK=64 chunks
#define BM 128
#define BN 128
#define GBK 64
#define GNCH (DM / GBK)                     // 16
#define GSTAGES 3
#define GPITCH 72
#define GTILE_B (128 * GPITCH * 2)          // 18432
#define GSTAGE_B (2 * GTILE_B)              // 36864
#define GEMM_SMEM (GSTAGES * GSTAGE_B)      // 110592

// attention smem
#define APITCH 72
#define AQ_B   (128 * APITCH * 2)           // 18432 (single Q)
#define AK_B   (64 * APITCH * 2)            // 9216 per K/V tile
#define ASTG_B (2 * AK_B)                   // 18432 per stage (K, V)
#define ASTAGES 4
#define APM_STRIDE 320
#define AOFF_Q  0
#define AOFF_ST AQ_B                          // 18432
#define AOFF_PM (AOFF_ST + ASTAGES * ASTG_B)  // 92160
#define ATTN_SMEM (AOFF_PM + ASTAGES * APM_STRIDE)  // 93440

// ---- scratch ----------------------------------------------------------------
__device__ __align__(256) __half g_x [MROWS * DM];
__device__ __align__(256) __half g_q [MROWS * DM];
__device__ __align__(256) __half g_k [MROWS * DM];
__device__ __align__(256) __half g_v [MROWS * DM];
__device__ __align__(256) __half g_a [MROWS * DM];
__device__ __align__(256) __half g_wf[4][DM * DM];        // W^T fp16: q,k,v,o

// ---- helpers ------------------------------------------------------------------
__device__ __forceinline__ uint32_t smem_to_u32(const void* p) {
    uint32_t a;
    asm("{ .reg .u64 t; cvta.to.shared.u64 t, %1; cvt.u32.u64 %0, t; }"
        : "=r"(a) : "l"(p));
    return a;
}
__device__ __forceinline__ void mma_f16(float* d, const uint32_t* a, const uint32_t* b) {
    asm volatile(
        "mma.sync.aligned.m16n8k16.row.col.f32.f16.f16.f32 "
        "{%0,%1,%2,%3}, {%4,%5,%6,%7}, {%8,%9}, {%0,%1,%2,%3};\n"
        : "+f"(d[0]), "+f"(d[1]), "+f"(d[2]), "+f"(d[3])
        : "r"(a[0]), "r"(a[1]), "r"(a[2]), "r"(a[3]), "r"(b[0]), "r"(b[1]));
}
__device__ __forceinline__ void ldsm_x4(uint32_t* r, uint32_t addr) {
    asm volatile("ldmatrix.sync.aligned.m8n8.x4.shared.b16 {%0,%1,%2,%3}, [%4];"
        : "=r"(r[0]), "=r"(r[1]), "=r"(r[2]), "=r"(r[3]) : "r"(addr));
}
__device__ __forceinline__ void ldsm_x4_t(uint32_t* r, uint32_t addr) {
    asm volatile("ldmatrix.sync.aligned.m8n8.x4.trans.shared.b16 {%0,%1,%2,%3}, [%4];"
        : "=r"(r[0]), "=r"(r[1]), "=r"(r[2]), "=r"(r[3]) : "r"(addr));
}
__device__ __forceinline__ void cpasync16(uint32_t dst, const void* src) {
    asm volatile("cp.async.cg.shared.global [%0], [%1], 16;" :: "r"(dst), "l"(src));
}
__device__ __forceinline__ uint32_t cvt_f16x2(float f_lo, float f_hi) {
    uint32_t r;
    asm("cvt.rn.f16x2.f32 %0, %1, %2;" : "=r"(r) : "f"(f_hi), "f"(f_lo));
    return r;
}
__device__ __forceinline__ uint32_t ex2_f16x2(uint32_t a) {
    uint32_t r;
    asm("ex2.approx.f16x2 %0, %1;" : "=r"(r) : "r"(a));
    return r;
}

// ---- GEMM body: single-pass fp16, BK=64, 3-stage ring (unchanged) ---------------
template<int OMODE>
__device__ __forceinline__ void gemm_body(
    const __half* A_, const __half* B_,
    float* __restrict__ C, __half* __restrict__ Ch, float scale)
{
    extern __shared__ char smem[];
    const uint32_t sb = smem_to_u32(smem);
    const int tid  = threadIdx.x;
    const int lane = tid & 31;
    const int wid  = tid >> 5;
    const int wm   = wid >> 2;
    const int wn   = wid & 3;
    const int bm = blockIdx.y, bn = blockIdx.x;

    const __half* gsrc[2] = {
        A_ + (size_t)bm * BM * DM,
        B_ + (size_t)bn * BN * DM
    };

    float acc[4][4][4];
#pragma unroll
    for (int i = 0; i < 4; i++)
#pragma unroll
        for (int j = 0; j < 4; j++)
#pragma unroll
            for (int r = 0; r < 4; r++) acc[i][j][r] = 0.f;

    auto issue = [&](int c) {
        if (c < GNCH) {
            const uint32_t sbase = sb + (c % GSTAGES) * GSTAGE_B;
            const size_t koff = (size_t)c * GBK;
#pragma unroll
            for (int i = 0; i < 8; i++) {
                int q = tid + i * 256;
                int t = q >> 10, r = (q >> 3) & 127, ch = q & 7;
                cpasync16(sbase + t * GTILE_B + (r * GPITCH + ch * 8) * 2,
                          gsrc[t] + (size_t)r * DM + koff + ch * 8);
            }
        }
        asm volatile("cp.async.commit_group;");
    };

    issue(0); issue(1);

    const int a_r = (lane & 7) + ((lane >> 3) & 1) * 8;
    const int a_c = (lane >> 4) * 8;
    const int b_r = (lane & 7) + ((lane >> 4) & 1) * 8;
    const int b_c = ((lane >> 3) & 1) * 8;

    for (int c = 0; c < GNCH; c++) {
        asm volatile("cp.async.wait_group %0;" :: "n"(1));
        __syncthreads();
        issue(c + 2);

        const uint32_t st = sb + (c % GSTAGES) * GSTAGE_B;
        const uint32_t sA = st, sB = st + GTILE_B;

#pragma unroll
        for (int k16 = 0; k16 < 4; k16++) {
            const int kc = k16 * 16;
            uint32_t ah[4][4], bh[2][4];
#pragma unroll
            for (int mfi = 0; mfi < 4; mfi++)
                ldsm_x4(ah[mfi], sA + ((wm * 64 + mfi * 16 + a_r) * GPITCH + kc + a_c) * 2);
#pragma unroll
            for (int nfp = 0; nfp < 2; nfp++)
                ldsm_x4(bh[nfp], sB + ((wn * 32 + nfp * 16 + b_r) * GPITCH + kc + b_c) * 2);
#pragma unroll
            for (int mfi = 0; mfi < 4; mfi++)
#pragma unroll
                for (int nf = 0; nf < 4; nf++)
                    mma_f16(acc[mfi][nf], ah[mfi], &bh[nf >> 1][(nf & 1) * 2]);
        }
    }

#pragma unroll
    for (int mfi = 0; mfi < 4; mfi++)
#pragma unroll
        for (int nf = 0; nf < 4; nf++) {
            int row = bm * BM + wm * 64 + mfi * 16 + (lane >> 2);
            int col = bn * BN + wn * 32 + nf * 8 + (lane & 3) * 2;
            float v0 = acc[mfi][nf][0] * scale, v1 = acc[mfi][nf][1] * scale;
            float v2 = acc[mfi][nf][2] * scale, v3 = acc[mfi][nf][3] * scale;
            if (OMODE == 0) {
                *(float2*)&C[(size_t)row * DM + col]       = make_float2(v0, v1);
                *(float2*)&C[(size_t)(row + 8) * DM + col] = make_float2(v2, v3);
            } else {
                *(uint32_t*)&Ch[(size_t)row * DM + col]       = cvt_f16x2(v0, v1);
                *(uint32_t*)&Ch[(size_t)(row + 8) * DM + col] = cvt_f16x2(v2, v3);
            }
        }
}

__global__ __launch_bounds__(256, 2)
void qkv_mma_kernel()
{
    const int z = blockIdx.z;
    if (z == 0)
        gemm_body<2>(g_x, g_wf[0], nullptr, g_q, ATT_SCALE * LOG2E);
    else if (z == 1)
        gemm_body<2>(g_x, g_wf[1], nullptr, g_k, 1.f);
    else
        gemm_body<2>(g_x, g_wf[2], nullptr, g_v, 1.f);
}
__global__ __launch_bounds__(256, 2)
void out_mma_kernel(float* __restrict__ out)
{
    gemm_body<0>(g_a, g_wf[3], out, nullptr, 1.f);
}

// ---- merged conversion: grid.x < XBLK -> x fp32->fp16; else W transpose ----------
#define XBLK (MROWS * DM / 4 / 256)   // 8192
__global__ __launch_bounds__(256)
void conv_all_kernel(const float* __restrict__ x,
                     const float* __restrict__ W0, const float* __restrict__ W1,
                     const float* __restrict__ W2, const float* __restrict__ W3)
{
    const int bid = blockIdx.x;
    const int tid = threadIdx.x;
    if (bid < XBLK) {
        int i = bid * 256 + tid;
        float4 v = ((const float4*)x)[i];
        ((uint32_t*)g_x)[i*2+0] = cvt_f16x2(v.x, v.y);
        ((uint32_t*)g_x)[i*2+1] = cvt_f16x2(v.z, v.w);
    } else {
        __shared__ float tile[32][33];
        const int wb = bid - XBLK;          // 0..4095
        const int z  = wb >> 10;            // 0..3
        const int t2 = wb & 1023;           // 32x32 tile index
        const float* W = (z == 0) ? W0 : (z == 1) ? W1 : (z == 2) ? W2 : W3;
        const int n0 = (t2 & 31) * 32, k0 = (t2 >> 5) * 32;
        const int tx = tid & 31, ty = tid >> 5;   // 32 x 8
#pragma unroll
        for (int i = ty; i < 32; i += 8)
            tile[i][tx] = W[(size_t)(k0 + i) * DM + n0 + tx];
        __syncthreads();
#pragma unroll
        for (int i = ty; i < 32; i += 8)
            g_wf[z][(size_t)(n0 + i) * DM + k0 + tx] = __float2half_rn(tile[tx][i]);
    }
}

// ---- Flash attention: f16x2 ex2, ones-mma l, pre-shuffle early-exit vote ----------
__global__ __launch_bounds__(256, 2)
void attn_kernel(const unsigned char* __restrict__ pad)
{
    extern __shared__ char smem[];
    const uint32_t sb = smem_to_u32(smem);
    const int tid = threadIdx.x, lane = tid & 31, wq = tid >> 5;
    const int b = blockIdx.y >> 4, h = blockIdx.y & 15;
    const int bx = (gridDim.x - 1) - blockIdx.x;   // heavy blocks first
    const int qbase = bx * 128;
    const int ntiles = bx * 2 + 2;

    // Q load (bundled into commit group 0)
    {
        const __half* srcq = g_q + (size_t)(b * SEQ + qbase) * DM + h * HD;
#pragma unroll
        for (int i = 0; i < 4; i++) {
            int q = tid + i * 256;
            int row = q >> 3, ch = q & 7;
            cpasync16(sb + AOFF_Q + (row * APITCH + ch * 8) * 2,
                      srcq + (size_t)row * DM + ch * 8);
        }
    }

    auto issue = [&](int t) {
        if (t < ntiles) {
            const int k0 = t * 64;
            const uint32_t sbase = sb + AOFF_ST + (t % ASTAGES) * ASTG_B;
            const __half* gs[2] = {
                g_k + (size_t)(b * SEQ + k0) * DM + h * HD,
                g_v + (size_t)(b * SEQ + k0) * DM + h * HD };
#pragma unroll
            for (int i = 0; i < 4; i++) {
                int q = tid + i * 256;
                int tt = q >> 9, row = (q >> 3) & 63, ch = q & 7;
                cpasync16(sbase + tt * AK_B + (row * APITCH + ch * 8) * 2,
                          gs[tt] + (size_t)row * DM + ch * 8);
            }
        }
        asm volatile("cp.async.commit_group;");
    };
    auto pmload = [&](int t) {
        if (t < ntiles && tid < 64) {
            unsigned char p = pad[b * SEQ + t * 64 + tid];
            float v = p ? -CUDART_INF_F : 0.f;
            const int stg = t % ASTAGES;
            *(float*)(smem + AOFF_PM + stg * APM_STRIDE + tid * 4) = v;
            unsigned bal = __ballot_sync(0xffffffff, p != 0);
            if ((tid & 31) == 0)
                *(uint32_t*)(smem + AOFF_PM + stg * APM_STRIDE + 256 + (tid >> 5) * 4) = bal;
        }
    };

    pmload(0); issue(0);
    pmload(1); issue(1);
    pmload(2); issue(2);

    const int r  = lane >> 2;
    const int c2 = (lane & 3) * 2;
    const int row0 = qbase + wq * 16 + r;
    const int row1 = row0 + 8;
    const int qmax = qbase + wq * 16 + 15;

    const int a_r = (lane & 7) + ((lane >> 3) & 1) * 8;
    const int a_c = (lane >> 4) * 8;
    const int b_r = (lane & 7) + ((lane >> 4) & 1) * 8;
    const int b_c = ((lane >> 3) & 1) * 8;
    const int v_r = (lane & 7) + ((lane >> 3) & 1) * 8;
    const int v_c = (lane >> 4) * 8;

    const uint32_t ONE2 = 0x3C003C00u;
    const uint32_t onesb[2] = {ONE2, ONE2};

    float m0 = -CUDART_INF_F, m1 = -CUDART_INF_F;
    float o_l[4] = {0.f, 0.f, 0.f, 0.f};
    float o[8][4];
#pragma unroll
    for (int i = 0; i < 8; i++)
#pragma unroll
        for (int j = 0; j < 4; j++) o[i][j] = 0.f;

    uint32_t qf[4][4];

    for (int t = 0; t < ntiles; t++) {
        asm volatile("cp.async.wait_group %0;" :: "n"(2));
        __syncthreads();

        if (t == 0) {
#pragma unroll
            for (int dk = 0; dk < 4; dk++)
                ldsm_x4(qf[dk], sb + AOFF_Q + ((wq * 16 + a_r) * APITCH + dk * 16 + a_c) * 2);
        }
        pmload(t + 3);
        issue(t + 3);

        const int k0 = t * 64;
        if (k0 <= qmax) {
            const uint32_t st = sb + AOFF_ST + (t % ASTAGES) * ASTG_B;

            // ---- S = Q K^T, single-pass fp16 ----
            float s[8][4];
#pragma unroll
            for (int f = 0; f < 8; f++)
#pragma unroll
                for (int j = 0; j < 4; j++) s[f][j] = 0.f;

#pragma unroll
            for (int dk = 0; dk < 4; dk++) {
                uint32_t kf[4][4];
#pragma unroll
                for (int g = 0; g < 4; g++)
                    ldsm_x4(kf[g], st + ((g * 16 + b_r) * APITCH + dk * 16 + b_c) * 2);
#pragma unroll
                for (int f = 0; f < 8; f++)
                    mma_f16(s[f], qf[dk], &kf[f >> 1][(f & 1) * 2]);
            }

            // ---- pad mask (only when this chunk has pad tokens) ----
            {
                const uint2 flg = *(const uint2*)(smem + AOFF_PM + (t % ASTAGES) * APM_STRIDE + 256);
                if (flg.x | flg.y) {
#pragma unroll
                    for (int f = 0; f < 8; f++) {
                        float2 pmv = *(float2*)(smem + AOFF_PM + (t % ASTAGES) * APM_STRIDE + (f * 8 + c2) * 4);
                        s[f][0] += pmv.x; s[f][1] += pmv.y;
                        s[f][2] += pmv.x; s[f][3] += pmv.y;
                    }
                }
            }
            // ---- causal mask (diagonal tiles only) ----
            if (k0 + 63 > row0) {
#pragma unroll
                for (int f = 0; f < 8; f++) {
                    int k = k0 + f * 8 + c2;
                    if (k     > row0) s[f][0] = -CUDART_INF_F;
                    if (k + 1 > row0) s[f][1] = -CUDART_INF_F;
                    if (k     > row1) s[f][2] = -CUDART_INF_F;
                    if (k + 1 > row1) s[f][3] = -CUDART_INF_F;
                }
            }

            // ---- online softmax (base 2): pre-shuffle early-exit vote ----
            // m0/m1 are quad-uniform, so "any lane's local max > m" is the exact
            // trigger for a max update; skip shuffles+rescale otherwise.
            float mx0 = -CUDART_INF_F, mx1 = -CUDART_INF_F;
#pragma unroll
            for (int f = 0; f < 8; f++) {
                mx0 = fmaxf(mx0, fmaxf(s[f][0], s[f][1]));
                mx1 = fmaxf(mx1, fmaxf(s[f][2], s[f][3]));
            }
            if (__any_sync(0xffffffff, (mx0 > m0) || (mx1 > m1))) {
                mx0 = fmaxf(mx0, __shfl_xor_sync(0xffffffff, mx0, 1));
                mx0 = fmaxf(mx0, __shfl_xor_sync(0xffffffff, mx0, 2));
                mx1 = fmaxf(mx1, __shfl_xor_sync(0xffffffff, mx1, 1));
                mx1 = fmaxf(mx1, __shfl_xor_sync(0xffffffff, mx1, 2));
                const float mn0 = fmaxf(m0, mx0), mn1 = fmaxf(m1, mx1);
                const float al0 = exp2f(m0 - mn0), al1 = exp2f(m1 - mn1);
                m0 = mn0; m1 = mn1;
                o_l[0] *= al0; o_l[2] *= al1;
#pragma unroll
                for (int nd = 0; nd < 8; nd++) {
                    o[nd][0] *= al0; o[nd][1] *= al0;
                    o[nd][2] *= al1; o[nd][3] *= al1;
                }
            }

            uint32_t pah[4][4];
#pragma unroll
            for (int f = 0; f < 8; f++) {
                const int ks = f >> 1, hi = (f & 1) * 2;
                pah[ks][hi]     = ex2_f16x2(cvt_f16x2(s[f][0] - m0, s[f][1] - m0));
                pah[ks][hi + 1] = ex2_f16x2(cvt_f16x2(s[f][2] - m1, s[f][3] - m1));
            }

            // ---- O += P V (+ ones-mma for l), single-pass fp16 ----
#pragma unroll
            for (int ks = 0; ks < 4; ks++) {
                uint32_t vf[4][4];
#pragma unroll
                for (int g = 0; g < 4; g++)
                    ldsm_x4_t(vf[g], st + AK_B + ((ks * 16 + v_r) * APITCH + g * 16 + v_c) * 2);
#pragma unroll
                for (int nd = 0; nd < 8; nd++)
                    mma_f16(o[nd], pah[ks], &vf[nd >> 1][(nd & 1) * 2]);
                mma_f16(o_l, pah[ks], onesb);   // row sums -> l
            }
        }
    }

    // ---- epilogue ----
    const float l0 = o_l[0], l1 = o_l[2];
    const float inv0 = (l0 > 0.f) ? (1.f / l0) : 0.f;
    const float inv1 = (l1 > 0.f) ? (1.f / l1) : 0.f;
    const size_t r0off = (size_t)(b * SEQ + row0) * DM + h * HD;
    const size_t r1off = (size_t)(b * SEQ + row1) * DM + h * HD;
#pragma unroll
    for (int nd = 0; nd < 8; nd++) {
        const int col = nd * 8 + c2;
        *(uint32_t*)&g_a[r0off + col] = cvt_f16x2(o[nd][0] * inv0, o[nd][1] * inv0);
        *(uint32_t*)&g_a[r1off + col] = cvt_f16x2(o[nd][2] * inv1, o[nd][3] * inv1);
    }
}

// ---- Launch ------------------------------------------------------------------------
extern "C" void kernel_launch(void* const* d_in, const int* in_sizes, int n_in,
                              void* d_out, int out_size)
{
    (void)in_sizes; (void)n_in; (void)out_size;
    const float*         x   = (const float*)d_in[0];
    const unsigned char* pad = (const unsigned char*)d_in[1];
    const float*         Wq  = (const float*)d_in[2];
    const float*         Wk  = (const float*)d_in[3];
    const float*         Wv  = (const float*)d_in[4];
    const float*         Wo  = (const float*)d_in[5];
    float*               out = (float*)d_out;

    cudaFuncSetAttribute(qkv_mma_kernel, cudaFuncAttributeMaxDynamicSharedMemorySize, GEMM_SMEM);
    cudaFuncSetAttribute(out_mma_kernel, cudaFuncAttributeMaxDynamicSharedMemorySize, GEMM_SMEM);
    cudaFuncSetAttribute(attn_kernel, cudaFuncAttributeMaxDynamicSharedMemorySize, ATTN_SMEM);

    conv_all_kernel<<<XBLK + 4096, 256>>>(x, Wq, Wk, Wv, Wo);

    qkv_mma_kernel<<<dim3(DM / BN, MROWS / BM, 3), 256, GEMM_SMEM>>>();

    attn_kernel<<<dim3(SEQ / 128, BATCH * NH), 256, ATTN_SMEM>>>(pad);

    out_mma_kernel<<<dim3(DM / BN, MROWS / BM), 256, GEMM_SMEM>>>(out);
}